// round 7
// baseline (speedup 1.0000x reference)
#include <cuda_runtime.h>
#include <math.h>
#include <stdint.h>

#define Bb 64
#define Ss 256
#define BS (Bb*Ss)
#define DL 300
#define DA 74
#define DV 35
#define DH 128

__device__ float g_seq[3u*BS*DH];
__device__ float g_xg_gru[6u*BS*192];
__device__ float g_x[3u*BS*DH];
__device__ float g_tstep[(unsigned)BS*384];
__device__ float g_sc[6u*(unsigned)Bb*Ss*Ss];
__device__ float g_xg_lstm[2u*BS*512];
__device__ float g_sf[(unsigned)BS*256];
__device__ float g_xg_rgn[2u*BS*384];
__device__ float g_rgn_out[2u*Bb*128];

typedef unsigned long long ull;

__device__ __forceinline__ uint32_t s2u(const void* p) {
    return (uint32_t)__cvta_generic_to_shared(p);
}
__device__ __forceinline__ void cpa16(uint32_t dst, const void* src, int bytes) {
    asm volatile("cp.async.cg.shared.global [%0], [%1], 16, %2;"
                 :: "r"(dst), "l"(src), "r"(bytes));
}
__device__ __forceinline__ void mma_tf32(float c[4], const uint32_t a[4], const uint32_t b[2]) {
    asm volatile(
        "mma.sync.aligned.m16n8k8.row.col.f32.tf32.tf32.f32 "
        "{%0,%1,%2,%3}, {%4,%5,%6,%7}, {%8,%9}, {%0,%1,%2,%3};"
        : "+f"(c[0]), "+f"(c[1]), "+f"(c[2]), "+f"(c[3])
        : "r"(a[0]), "r"(a[1]), "r"(a[2]), "r"(a[3]), "r"(b[0]), "r"(b[1]));
}
__device__ __forceinline__ ull pk(float x, float y) {
    ull r; asm("mov.b64 %0,{%1,%2};" : "=l"(r) : "f"(x), "f"(y)); return r;
}
__device__ __forceinline__ float2 upk(ull v) {
    float2 f; asm("mov.b64 {%0,%1},%2;" : "=f"(f.x), "=f"(f.y) : "l"(v)); return f;
}
__device__ __forceinline__ void ffma2(ull &d, ull a, ull b) {
    asm volatile("fma.rn.f32x2 %0, %1, %2, %0;" : "+l"(d) : "l"(a), "l"(b));
}
__device__ __forceinline__ void lds2x64(ull &a, ull &b, uint32_t addr) {
    asm volatile("ld.shared.v2.b64 {%0,%1},[%2];" : "=l"(a), "=l"(b) : "r"(addr));
}
__device__ __forceinline__ float sigf(float x) { return 1.f/(1.f + __expf(-x)); }
__device__ __forceinline__ float tanhfast(float x) {
    float y; asm("tanh.approx.f32 %0,%1;" : "=f"(y) : "f"(x)); return y;
}

// ---------------------------------------------------------------------------
// TF32 tensor-core GEMM, 3-stage cp.async pipeline, z-batched.
// MODE 0: generic z-batched NN; MODE 1: GRU (A shared per 2 z); MODE 3: merged
// PV — two K=256 segments (kv1, kv2) accumulated into one tile, += into tstep.
// ---------------------------------------------------------------------------
#define ASTR 36
#define BSTR 136
#define AWORDS (128*ASTR)          // 4608
#define STG_WORDS (2*AWORDS)       // 9216 per stage

template<int MODE, bool TRANSB, bool ACC, bool PIPE, bool GATHER>
__launch_bounds__(256, 2)
__global__ void gemm_tc(const float* __restrict__ A, const float* __restrict__ B,
                        const float* __restrict__ bias, float* __restrict__ C,
                        int M, int N, int K,
                        long sA, long sB, long sBias, long sC, int ldc,
                        float scale, const int* __restrict__ gidx, int aux)
{
    extern __shared__ uint32_t smp[];
    const int kvtab[6] = {1,2,0,2,0,1};

    int z = blockIdx.z;
    const float *Ab = nullptr, *Bp = nullptr, *bp = nullptr;
    float* Cb;
    if (MODE == 0 || MODE == 1) {
        Ab = A + (MODE==1 ? (long)(z>>1)*sA : (long)z*sA);
        Bp = B + (long)z*sB;
        bp = bias ? bias + (long)z*sBias : nullptr;
        Cb = C + (long)z*sC;
    } else { // MODE 3 merged PV
        int qq = z>>6, b = z&63;
        Cb = C + (long)qq*128 + (long)b*Ss*384;
    }

    int m0 = blockIdx.y*128, n0 = blockIdx.x*128;
    int tid = threadIdx.x;
    int warp = tid>>5, lane = tid&31;
    int g = lane>>2, tig = lane&3;
    int wm = (warp&1)*64, wn = (warp>>1)*32;

    float c[4][4][4];
#pragma unroll
    for (int mt=0;mt<4;mt++)
#pragma unroll
        for (int nt=0;nt<4;nt++)
#pragma unroll
            for (int i=0;i<4;i++) c[mt][nt][i]=0.f;

    int lrow = tid>>3;
    int akq  = (tid&7)*4;
    const float* arp[4];
    const float* brp[4];
    int bnk = tid>>5;
    int bn4 = (tid&31)*4;

    auto setup_rows = [&]() {
#pragma unroll
        for (int p=0;p<4;p++) {
            long grow = m0 + lrow + p*32;
            long r = GATHER ? (long)gidx[grow] : grow;
            arp[p] = Ab + r*(long)K;
        }
        if (TRANSB) {
#pragma unroll
            for (int p=0;p<4;p++) brp[p] = Bp + (long)(n0 + lrow + p*32)*K;
        }
    };

    auto load_tile = [&](int st, int k0) {
        uint32_t* As = smp + st*STG_WORDS;
        uint32_t* Bs = As + AWORDS;
        if (PIPE) {
#pragma unroll
            for (int p=0;p<4;p++) {
                int gk = k0 + akq;
                int bytes = (K - gk)*4; bytes = bytes<0?0:(bytes>16?16:bytes);
                const float* src = bytes ? (arp[p] + gk) : Ab;
                cpa16(s2u(&As[(lrow + p*32)*ASTR + akq]), src, bytes);
            }
            if (TRANSB) {
#pragma unroll
                for (int p=0;p<4;p++) {
                    int gk = k0 + akq;
                    int bytes = (K - gk)*4; bytes = bytes<0?0:(bytes>16?16:bytes);
                    const float* src = bytes ? (brp[p] + gk) : Bp;
                    cpa16(s2u(&Bs[(lrow + p*32)*ASTR + akq]), src, bytes);
                }
            } else {
#pragma unroll
                for (int p=0;p<4;p++) {
                    int k = bnk + p*8;
                    int ok = ((k0+k) < K) && ((n0+bn4) < N);
                    const float* src = ok ? (Bp + (long)(k0+k)*N + n0 + bn4) : Bp;
                    cpa16(s2u(&Bs[k*BSTR + bn4]), src, ok ? 16 : 0);
                }
            }
        } else {
#pragma unroll
            for (int p=0;p<4;p++) {
                int gk = k0 + akq;
                uint4 u = {0u,0u,0u,0u};
                const float* ap = arp[p];
                if (gk+0 < K) u.x = __float_as_uint(ap[gk+0]);
                if (gk+1 < K) u.y = __float_as_uint(ap[gk+1]);
                if (gk+2 < K) u.z = __float_as_uint(ap[gk+2]);
                if (gk+3 < K) u.w = __float_as_uint(ap[gk+3]);
                *(uint4*)&As[(lrow + p*32)*ASTR + akq] = u;
            }
#pragma unroll
            for (int p=0;p<4;p++) {
                int k = bnk + p*8;
                uint4 u = {0u,0u,0u,0u};
                if ((k0+k) < K && (n0+bn4) < N) {
                    const float* bpr = Bp + (long)(k0+k)*N + n0 + bn4;
                    u.x = __float_as_uint(bpr[0]); u.y = __float_as_uint(bpr[1]);
                    u.z = __float_as_uint(bpr[2]); u.w = __float_as_uint(bpr[3]);
                }
                *(uint4*)&Bs[k*BSTR + bn4] = u;
            }
        }
    };

    auto compute = [&](int st) {
        const uint32_t* As = smp + st*STG_WORDS;
        const uint32_t* Bs = As + AWORDS;
#pragma unroll
        for (int ks=0;ks<4;ks++) {
            uint32_t a[4][4], b[4][2];
#pragma unroll
            for (int mt=0;mt<4;mt++) {
                int base = (wm + mt*16 + g)*ASTR + ks*8 + tig;
                a[mt][0] = As[base];
                a[mt][1] = As[base + 8*ASTR];
                a[mt][2] = As[base + 4];
                a[mt][3] = As[base + 8*ASTR + 4];
            }
#pragma unroll
            for (int nt=0;nt<4;nt++) {
                if (TRANSB) {
                    int base = (wn + nt*8 + g)*ASTR + ks*8 + tig;
                    b[nt][0] = Bs[base];
                    b[nt][1] = Bs[base + 4];
                } else {
                    int base = (ks*8 + tig)*BSTR + wn + nt*8 + g;
                    b[nt][0] = Bs[base];
                    b[nt][1] = Bs[base + 4*BSTR];
                }
            }
#pragma unroll
            for (int mt=0;mt<4;mt++)
#pragma unroll
                for (int nt=0;nt<4;nt++)
                    mma_tf32(c[mt][nt], a[mt], b[nt]);
        }
    };

    int nseg = (MODE==3) ? 2 : 1;
    int ktn = (K+31)>>5;
    for (int seg=0; seg<nseg; seg++) {
        if (MODE==3) {
            int qq = z>>6, b = z&63;
            int p = 2*qq + seg;
            Ab = A + ((long)p*64 + b)*(long)Ss*Ss;
            Bp = B + ((long)kvtab[p]*BS + (long)b*Ss)*128;
        }
        setup_rows();
        if (seg) {
            asm volatile("cp.async.wait_group 0;");
            __syncthreads();
        }
        if (PIPE) {
            load_tile(0, 0);
            asm volatile("cp.async.commit_group;");
            if (ktn > 1) load_tile(1, 32);
            asm volatile("cp.async.commit_group;");
            for (int kt=0; kt<ktn; kt++) {
                asm volatile("cp.async.wait_group 1;");
                __syncthreads();
                if (kt+2 < ktn) load_tile((kt+2)%3, (kt+2)*32);
                asm volatile("cp.async.commit_group;");
                compute(kt%3);
            }
        } else {
            for (int kt=0; kt<ktn; kt++) {
                load_tile(0, kt*32);
                __syncthreads();
                compute(0);
                __syncthreads();
            }
        }
    }
    __syncthreads();

#pragma unroll
    for (int mt=0;mt<4;mt++) {
        long m = m0 + wm + mt*16 + g;
#pragma unroll
        for (int nt=0;nt<4;nt++) {
            int n = n0 + wn + nt*8 + tig*2;
            if (n < N) {
                float bx=0.f, by=0.f;
                if (bp) { bx = bp[n]; by = bp[n+1]; }
                float* p0 = Cb + m*ldc + n;
                float* p1 = p0 + 8l*ldc;
                float2 v0, v1;
                v0.x = c[mt][nt][0]*scale + bx;
                v0.y = c[mt][nt][1]*scale + by;
                v1.x = c[mt][nt][2]*scale + bx;
                v1.y = c[mt][nt][3]*scale + by;
                if (ACC) {
                    float2 o0 = *(const float2*)p0, o1 = *(const float2*)p1;
                    v0.x+=o0.x; v0.y+=o0.y; v1.x+=o1.x; v1.y+=o1.y;
                }
                *(float2*)p0 = v0;
                *(float2*)p1 = v1;
            }
        }
    }
}

// ---------------------------------------------------------------------------
// Fused QK^T + scale + softmax. Block tile 128x256 (full S rows), warp tile
// 64x64, K=128, 3-stage cp.async. Writes normalized P to sc.
// grid (1, 2, 384): y = m-tile, z = pair*64 + b.
// ---------------------------------------------------------------------------
#define QKA 4608               // 128*36
#define QKB 9216               // 256*36
#define QKSTG (QKA+QKB)

__launch_bounds__(256, 1)
__global__ void qk_softmax(const float* __restrict__ x, float* __restrict__ sc,
                           float scale)
{
    extern __shared__ uint32_t smp[];
    const int qtab[6]  = {0,0,1,1,2,2};
    const int kvtab[6] = {1,2,0,2,0,1};

    int z = blockIdx.z;
    int p = z>>6, b = z&63;
    const float* Ab = x + ((long)qtab[p]*BS + (long)b*Ss)*128;
    const float* Bp = x + ((long)kvtab[p]*BS + (long)b*Ss)*128;
    float* Cb = sc + (long)z*Ss*Ss;
    int m0 = blockIdx.y*128;
    int tid = threadIdx.x;
    int warp = tid>>5, lane = tid&31;
    int g = lane>>2, tig = lane&3;
    int wm = (warp&1)*64, wn = (warp>>1)*64;

    float c[4][8][4];
#pragma unroll
    for (int mt=0;mt<4;mt++)
#pragma unroll
        for (int nt=0;nt<8;nt++)
#pragma unroll
            for (int i=0;i<4;i++) c[mt][nt][i]=0.f;

    int lrow = tid>>3;
    int akq  = (tid&7)*4;
    const float* arp[4];
#pragma unroll
    for (int q=0;q<4;q++) arp[q] = Ab + (long)(m0 + lrow + q*32)*128;
    const float* brp[8];
#pragma unroll
    for (int q=0;q<8;q++) brp[q] = Bp + (long)(lrow + q*32)*128;

    auto load_tile = [&](int st, int k0) {
        uint32_t* As = smp + st*QKSTG;
        uint32_t* Bs = As + QKA;
#pragma unroll
        for (int q=0;q<4;q++)
            cpa16(s2u(&As[(lrow + q*32)*ASTR + akq]), arp[q] + k0 + akq, 16);
#pragma unroll
        for (int q=0;q<8;q++)
            cpa16(s2u(&Bs[(lrow + q*32)*ASTR + akq]), brp[q] + k0 + akq, 16);
    };
    auto compute = [&](int st) {
        const uint32_t* As = smp + st*QKSTG;
        const uint32_t* Bs = As + QKA;
#pragma unroll
        for (int ks=0;ks<4;ks++) {
            uint32_t a[4][4], bb[8][2];
#pragma unroll
            for (int mt=0;mt<4;mt++) {
                int base = (wm + mt*16 + g)*ASTR + ks*8 + tig;
                a[mt][0] = As[base];
                a[mt][1] = As[base + 8*ASTR];
                a[mt][2] = As[base + 4];
                a[mt][3] = As[base + 8*ASTR + 4];
            }
#pragma unroll
            for (int nt=0;nt<8;nt++) {
                int base = (wn + nt*8 + g)*ASTR + ks*8 + tig;
                bb[nt][0] = Bs[base];
                bb[nt][1] = Bs[base + 4];
            }
#pragma unroll
            for (int mt=0;mt<4;mt++)
#pragma unroll
                for (int nt=0;nt<8;nt++)
                    mma_tf32(c[mt][nt], a[mt], bb[nt]);
        }
    };

    load_tile(0, 0);
    asm volatile("cp.async.commit_group;");
    load_tile(1, 32);
    asm volatile("cp.async.commit_group;");
    for (int kt=0; kt<4; kt++) {
        asm volatile("cp.async.wait_group 1;");
        __syncthreads();
        if (kt+2 < 4) load_tile((kt+2)%3, (kt+2)*32);
        asm volatile("cp.async.commit_group;");
        compute(kt%3);
    }
    asm volatile("cp.async.wait_group 0;");
    __syncthreads();

    // ---- fused softmax over 256 cols ----
    // scale first
#pragma unroll
    for (int mt=0;mt<4;mt++)
#pragma unroll
        for (int nt=0;nt<8;nt++)
#pragma unroll
            for (int i=0;i<4;i++) c[mt][nt][i] *= scale;

    float* red = (float*)smp;         // [128][4]
    int wcol = warp>>1;
    float rmax[4][2], rinv[4][2];

    // pass 1: row max
#pragma unroll
    for (int mt=0;mt<4;mt++)
#pragma unroll
        for (int h=0;h<2;h++) {
            float m = -1e30f;
#pragma unroll
            for (int nt=0;nt<8;nt++)
                m = fmaxf(m, fmaxf(c[mt][nt][2*h], c[mt][nt][2*h+1]));
            m = fmaxf(m, __shfl_xor_sync(0xffffffffu, m, 1));
            m = fmaxf(m, __shfl_xor_sync(0xffffffffu, m, 2));
            if (tig == 0) red[(wm + mt*16 + g + h*8)*4 + wcol] = m;
        }
    __syncthreads();
#pragma unroll
    for (int mt=0;mt<4;mt++)
#pragma unroll
        for (int h=0;h<2;h++) {
            int r = wm + mt*16 + g + h*8;
            rmax[mt][h] = fmaxf(fmaxf(red[r*4], red[r*4+1]),
                                fmaxf(red[r*4+2], red[r*4+3]));
        }
    __syncthreads();
    // pass 2: exp + row sum
#pragma unroll
    for (int mt=0;mt<4;mt++)
#pragma unroll
        for (int h=0;h<2;h++) {
            float s = 0.f;
#pragma unroll
            for (int nt=0;nt<8;nt++) {
                float e0 = __expf(c[mt][nt][2*h]   - rmax[mt][h]);
                float e1 = __expf(c[mt][nt][2*h+1] - rmax[mt][h]);
                c[mt][nt][2*h]   = e0;
                c[mt][nt][2*h+1] = e1;
                s += e0 + e1;
            }
            s += __shfl_xor_sync(0xffffffffu, s, 1);
            s += __shfl_xor_sync(0xffffffffu, s, 2);
            if (tig == 0) red[(wm + mt*16 + g + h*8)*4 + wcol] = s;
        }
    __syncthreads();
#pragma unroll
    for (int mt=0;mt<4;mt++)
#pragma unroll
        for (int h=0;h<2;h++) {
            int r = wm + mt*16 + g + h*8;
            rinv[mt][h] = 1.f/(red[r*4] + red[r*4+1] + red[r*4+2] + red[r*4+3]);
        }
    // write P
#pragma unroll
    for (int mt=0;mt<4;mt++)
#pragma unroll
        for (int h=0;h<2;h++) {
            long row = m0 + wm + mt*16 + g + h*8;
#pragma unroll
            for (int nt=0;nt<8;nt++) {
                int col = wn + nt*8 + tig*2;
                float2 v;
                v.x = c[mt][nt][2*h]   * rinv[mt][h];
                v.y = c[mt][nt][2*h+1] * rinv[mt][h];
                *(float2*)&Cb[row*256 + col] = v;
            }
        }
}

// ---------------------------------------------------------------------------
// biGRU: grid 3*2*64, 192 thr; k-packed f32x2, all weights in regs.
// ---------------------------------------------------------------------------
__launch_bounds__(192, 3)
__global__ void gru_rec(const float* __restrict__ xg_all, const float* __restrict__ Wh,
                        const float* __restrict__ bh, float* __restrict__ x_out,
                        float* __restrict__ tstep)
{
    int bx = blockIdx.x;
    int m = bx>>7, d = (bx>>6)&1, b = bx&63, md = m*2+d;
    int j = threadIdx.x;
    ull w2[32];
#pragma unroll
    for (int q=0;q<32;q++)
        w2[q] = pk(Wh[((long)md*64 + 2*q)*192 + j], Wh[((long)md*64 + 2*q+1)*192 + j]);
    float bhj = bh[md*192 + j];
    __shared__ alignas(16) float h_s[64];
    __shared__ float pre_s[192], xn_s[64];
    uint32_t hsa = s2u(h_s);
    if (j<64) h_s[j]=0.f;
    const float* xg = xg_all + ((long)md*BS + (long)b*Ss)*192;
    for (int t=0;t<Ss;t++) {
        int s = d ? (Ss-1-t) : t;
        __syncthreads();
        ull a0 = pk(bhj, 0.f), a1 = pk(0.f, 0.f);
#pragma unroll
        for (int q=0;q<16;q++) {
            ull h0,h1; lds2x64(h0,h1, hsa + q*16);
            ffma2(a0, h0, w2[2*q]);
            ffma2(a1, h1, w2[2*q+1]);
        }
        float2 f0 = upk(a0), f1 = upk(a1);
        float acc = f0.x + f0.y + f1.x + f1.y;
        float xgv = xg[(long)s*192 + j];
        if (j<128) pre_s[j] = acc + xgv;
        else { pre_s[j] = acc; xn_s[j-128] = xgv; }
        __syncthreads();
        if (j<64) {
            float r = sigf(pre_s[j]);
            float zg = sigf(pre_s[64+j]);
            float n = tanhfast(xn_s[j] + r*pre_s[128+j]);
            float hn = (1.f-zg)*n + zg*h_s[j];
            h_s[j] = hn;
            long row = (long)b*Ss + s;
            x_out[((long)m*BS + row)*128 + d*64 + j] = hn;
            tstep[row*384 + m*128 + d*64 + j] = hn;
        }
    }
}

// ---------------------------------------------------------------------------
// biLSTM: grid 2*64, 512 thr; k-packed f32x2, k<96 regs + k>=96 smem.
// ---------------------------------------------------------------------------
__launch_bounds__(512, 1)
__global__ void lstm_rec(const float* __restrict__ xg_all, const float* __restrict__ Wh,
                         const float* __restrict__ bh, float* __restrict__ sf)
{
    extern __shared__ unsigned char smraw[];
    ull*   Wlo2  = (ull*)smraw;                         // [16][512]
    float* h_s   = (float*)(smraw + 16*512*8);          // 128
    float* pre_s = (float*)(smraw + 16*512*8 + 512);    // 512
    int bx = blockIdx.x, d = bx>>6, b = bx&63;
    int j = threadIdx.x;
    const float* Whd = Wh + (long)d*128*512;
    ull w2[48];
#pragma unroll
    for (int q=0;q<48;q++)
        w2[q] = pk(Whd[(long)(2*q)*512 + j], Whd[(long)(2*q+1)*512 + j]);
    for (int q=0;q<16;q++)
        Wlo2[q*512 + j] = pk(Whd[(long)(96+2*q)*512 + j], Whd[(long)(97+2*q)*512 + j]);
    float bhj = bh[d*512 + j];
    float c = 0.f;
    if (j<128) h_s[j]=0.f;
    uint32_t hsa = s2u(h_s);
    const float* xg = xg_all + ((long)d*BS + (long)b*Ss)*512;
    for (int t=0;t<Ss;t++) {
        int s = d ? (Ss-1-t) : t;
        __syncthreads();
        ull a0 = pk(bhj, 0.f), a1 = pk(0.f, 0.f);
#pragma unroll
        for (int q=0;q<24;q++) {
            ull h0,h1; lds2x64(h0,h1, hsa + q*16);
            ffma2(a0, h0, w2[2*q]);
            ffma2(a1, h1, w2[2*q+1]);
        }
#pragma unroll
        for (int q=0;q<8;q++) {
            ull h0,h1; lds2x64(h0,h1, hsa + 384 + q*16);
            ffma2(a0, h0, Wlo2[(2*q)*512 + j]);
            ffma2(a1, h1, Wlo2[(2*q+1)*512 + j]);
        }
        float2 f0 = upk(a0), f1 = upk(a1);
        float acc = f0.x + f0.y + f1.x + f1.y + xg[(long)s*512 + j];
        pre_s[j] = acc;
        __syncthreads();
        if (j<128) {
            float ig = pre_s[j], fg = pre_s[128+j], gg = pre_s[256+j], og = pre_s[384+j];
            c = sigf(fg)*c + sigf(ig)*tanhfast(gg);
            float h = sigf(og)*tanhfast(c);
            h_s[j] = h;
            sf[((long)b*Ss + s)*256 + d*128 + j] = h;
        }
    }
}

// ---------------------------------------------------------------------------
// RGN: grid 2*64, 384 thr; k-packed f32x2, ALL 128 k in regs.
// ---------------------------------------------------------------------------
__launch_bounds__(384, 1)
__global__ void rgn_rec(const float* __restrict__ xg_all, const float* __restrict__ Wh,
                        const float* __restrict__ state0, const float* __restrict__ state1,
                        float* __restrict__ outbuf)
{
    __shared__ alignas(16) float h_s[128];
    __shared__ float pre_s[384], xn_s[128];
    int bx = blockIdx.x, kk = bx>>6, b = bx&63;
    int j = threadIdx.x;
    const float* Whd = Wh + (long)kk*128*384;
    ull w2[64];
#pragma unroll
    for (int q=0;q<64;q++)
        w2[q] = pk(Whd[(long)(2*q)*384 + j], Whd[(long)(2*q+1)*384 + j]);
    if (j<128) h_s[j] = (kk==0?state0:state1)[b*128 + j];
    uint32_t hsa = s2u(h_s);
    const float* xg = xg_all + ((long)kk*BS + (long)b*Ss)*384;
    for (int t=0;t<Ss;t++) {
        int s = kk ? (Ss-1-t) : t;
        __syncthreads();
        ull a0 = pk(0.f, 0.f), a1 = pk(0.f, 0.f);
#pragma unroll
        for (int q=0;q<32;q++) {
            ull h0,h1; lds2x64(h0,h1, hsa + q*16);
            ffma2(a0, h0, w2[2*q]);
            ffma2(a1, h1, w2[2*q+1]);
        }
        float2 f0 = upk(a0), f1 = upk(a1);
        float acc = f0.x + f0.y + f1.x + f1.y;
        float xgv = xg[(long)s*384 + j];
        if (j<256) pre_s[j] = acc + xgv;
        else { pre_s[j] = acc; xn_s[j-256] = xgv; }
        __syncthreads();
        if (j<128) {
            float r = sigf(pre_s[j]);
            float z = sigf(pre_s[128+j]);
            float n = tanhfast(xn_s[j] + r*pre_s[256+j]);
            h_s[j] = (1.f-z)*n + z*h_s[j];
        }
    }
    __syncthreads();
    if (j<128) outbuf[((long)kk*64 + b)*128 + j] = h_s[j];
}

__launch_bounds__(32)
__global__ void final_fc(const float* __restrict__ outbuf,
                         const float* __restrict__ fc1W, const float* __restrict__ fc1b,
                         const float* __restrict__ fc2W, const float* __restrict__ fc2b,
                         float* __restrict__ out)
{
    int b = blockIdx.x, t = threadIdx.x;
    float acc = fc1b[t];
    for (int k=0;k<128;k++) {
        float x = outbuf[b*128+k] + outbuf[64*128 + b*128 + k];
        acc += x * fc1W[k*32 + t];
    }
    float h = acc > 0.f ? acc : 0.01f*acc;
    float v = h * fc2W[t];
#pragma unroll
    for (int o=16;o;o>>=1) v += __shfl_xor_sync(0xffffffffu, v, o);
    if (t==0) out[b] = v + fc2b[0];
}

extern "C" void kernel_launch(void* const* d_in, const int* in_sizes, int n_in,
                              void* d_out, int out_size)
{
    (void)in_sizes; (void)n_in; (void)out_size;
    const int*   sentences = (const int*)  d_in[0];
    const float* acoustic  = (const float*)d_in[1];
    const float* video     = (const float*)d_in[2];
    const float* state0    = (const float*)d_in[3];
    const float* state1    = (const float*)d_in[4];
    const float* emb       = (const float*)d_in[5];
    const float* proj_l_W  = (const float*)d_in[6];
    const float* proj_l_b  = (const float*)d_in[7];
    const float* proj_a_W  = (const float*)d_in[8];
    const float* proj_a_b  = (const float*)d_in[9];
    const float* proj_v_W  = (const float*)d_in[10];
    const float* proj_v_b  = (const float*)d_in[11];
    const float* gru_Wi    = (const float*)d_in[12];
    const float* gru_Wh    = (const float*)d_in[13];
    const float* gru_bi    = (const float*)d_in[14];
    const float* gru_bh    = (const float*)d_in[15];
    const float* lstm_Wi   = (const float*)d_in[16];
    const float* lstm_Wh   = (const float*)d_in[17];
    const float* lstm_bi   = (const float*)d_in[18];
    const float* lstm_bh   = (const float*)d_in[19];
    const float* rgn_Wx    = (const float*)d_in[20];
    const float* rgn_Wh    = (const float*)d_in[21];
    const float* rgn_b     = (const float*)d_in[22];
    const float* fc1_W     = (const float*)d_in[23];
    const float* fc1_b     = (const float*)d_in[24];
    const float* fc2_W     = (const float*)d_in[25];
    const float* fc2_b     = (const float*)d_in[26];
    float* out = (float*)d_out;

    float *seq,*xg_gru,*x,*tstep,*sc,*xg_lstm,*sf,*xg_rgn,*rgn_out;
    cudaGetSymbolAddress((void**)&seq, g_seq);
    cudaGetSymbolAddress((void**)&xg_gru, g_xg_gru);
    cudaGetSymbolAddress((void**)&x, g_x);
    cudaGetSymbolAddress((void**)&tstep, g_tstep);
    cudaGetSymbolAddress((void**)&sc, g_sc);
    cudaGetSymbolAddress((void**)&xg_lstm, g_xg_lstm);
    cudaGetSymbolAddress((void**)&sf, g_sf);
    cudaGetSymbolAddress((void**)&xg_rgn, g_xg_rgn);
    cudaGetSymbolAddress((void**)&rgn_out, g_rgn_out);

    const size_t shm3 = 3u*STG_WORDS*4u;    // 110592 B
    const size_t shm1 = 1u*STG_WORDS*4u;    // 36864 B
    const size_t shmq = 3u*QKSTG*4u;        // 165888 B
    cudaFuncSetAttribute(gemm_tc<0,false,false,true,true>,   cudaFuncAttributeMaxDynamicSharedMemorySize, (int)shm3);
    cudaFuncSetAttribute(gemm_tc<0,false,false,true,false>,  cudaFuncAttributeMaxDynamicSharedMemorySize, (int)shm3);
    cudaFuncSetAttribute(gemm_tc<0,false,false,false,false>, cudaFuncAttributeMaxDynamicSharedMemorySize, (int)shm1);
    cudaFuncSetAttribute(gemm_tc<1,false,false,true,false>,  cudaFuncAttributeMaxDynamicSharedMemorySize, (int)shm3);
    cudaFuncSetAttribute(gemm_tc<3,false,true ,true,false>,  cudaFuncAttributeMaxDynamicSharedMemorySize, (int)shm3);
    cudaFuncSetAttribute(qk_softmax, cudaFuncAttributeMaxDynamicSharedMemorySize, (int)shmq);
    cudaFuncSetAttribute(lstm_rec, cudaFuncAttributeMaxDynamicSharedMemorySize, 72*1024);

    // modality projections
    gemm_tc<0,false,false,true,true><<<dim3(1, BS/128, 1), 256, shm3>>>(
        emb, proj_l_W, proj_l_b, seq, BS, 128, DL, 0,0,0,0, 128, 1.f, sentences, 0);
    gemm_tc<0,false,false,false,false><<<dim3(1, BS/128, 1), 256, shm1>>>(
        acoustic, proj_a_W, proj_a_b, seq + 1l*BS*DH, BS, 128, DA, 0,0,0,0, 128, 1.f, nullptr, 0);
    gemm_tc<0,false,false,false,false><<<dim3(1, BS/128, 1), 256, shm1>>>(
        video, proj_v_W, proj_v_b, seq + 2l*BS*DH, BS, 128, DV, 0,0,0,0, 128, 1.f, nullptr, 0);

    // GRU input projections (batched z=6)
    gemm_tc<1,false,false,true,false><<<dim3(2, BS/128, 6), 256, shm3>>>(
        seq, gru_Wi, gru_bi, xg_gru, BS, 192, 128,
        (long)BS*DH, 128l*192, 192, (long)BS*192, 192, 1.f, nullptr, 0);

    gru_rec<<<3*2*64, 192>>>(xg_gru, gru_Wh, gru_bh, x, tstep);

    // JCAF: fused QK^T+softmax, then merged PV (+= into tstep)
    const float scale = 0.08838834764831845f;
    qk_softmax<<<dim3(1, 2, 384), 256, shmq>>>(x, sc, scale);
    gemm_tc<3,false,true,true,false><<<dim3(1, 2, 192), 256, shm3>>>(
        sc, x, nullptr, tstep, 256, 128, 256, 0,0,0,0, 384, 1.f, nullptr, 0);

    // LSTM input projections (batched z=2)
    gemm_tc<0,false,false,true,false><<<dim3(4, BS/128, 2), 256, shm3>>>(
        tstep, lstm_Wi, lstm_bi, xg_lstm, BS, 512, 384,
        0, 384l*512, 512, (long)BS*512, 512, 1.f, nullptr, 0);

    lstm_rec<<<2*64, 512, 16*512*8 + 512 + 2048>>>(xg_lstm, lstm_Wh, lstm_bh, sf);

    // RGN input projections (batched z=2)
    gemm_tc<0,false,false,true,false><<<dim3(3, BS/128, 2), 256, shm3>>>(
        sf, rgn_Wx, rgn_b, xg_rgn, BS, 384, 256,
        0, 256l*384, 384, (long)BS*384, 384, 1.f, nullptr, 0);

    rgn_rec<<<2*64, 384>>>(xg_rgn, rgn_Wh, state0, state1, rgn_out);

    final_fc<<<Bb, 32>>>(rgn_out, fc1_W, fc1_b, fc2_W, fc2_b, out);
}

// round 8
// speedup vs baseline: 1.0977x; 1.0977x over previous
#include <cuda_runtime.h>
#include <cuda_fp16.h>
#include <math.h>
#include <stdint.h>

#define Bb 64
#define Ss 256
#define BS (Bb*Ss)
#define DL 300
#define DA 74
#define DV 35
#define DH 128

// fp32 scratch
__device__ float g_xg_gru[6u*BS*192];
__device__ float g_tstep[(unsigned)BS*384];
__device__ float g_xg_lstm[2u*BS*512];
__device__ float g_xg_rgn[2u*BS*384];
__device__ float g_rgn_out[2u*Bb*128];
// fp16 scratch
__device__ __half g_seq_h[3u*BS*DH];
__device__ __half g_x_h[3u*BS*DH];
__device__ __half g_xT_h[3u*(unsigned)Bb*128*Ss];
__device__ __half g_P_h[6u*(unsigned)Bb*Ss*Ss];
__device__ __half g_tstep_h[(unsigned)BS*384];
__device__ __half g_sf_h[(unsigned)BS*256];
__device__ __half g_WT_h[6*192*128 + 2*512*384 + 2*384*256];

typedef unsigned long long ull;

__device__ __forceinline__ uint32_t s2u(const void* p) {
    return (uint32_t)__cvta_generic_to_shared(p);
}
__device__ __forceinline__ void cpa16(uint32_t dst, const void* src, int bytes) {
    asm volatile("cp.async.cg.shared.global [%0], [%1], 16, %2;"
                 :: "r"(dst), "l"(src), "r"(bytes));
}
__device__ __forceinline__ void mma_tf32(float c[4], const uint32_t a[4], const uint32_t b[2]) {
    asm volatile(
        "mma.sync.aligned.m16n8k8.row.col.f32.tf32.tf32.f32 "
        "{%0,%1,%2,%3}, {%4,%5,%6,%7}, {%8,%9}, {%0,%1,%2,%3};"
        : "+f"(c[0]), "+f"(c[1]), "+f"(c[2]), "+f"(c[3])
        : "r"(a[0]), "r"(a[1]), "r"(a[2]), "r"(a[3]), "r"(b[0]), "r"(b[1]));
}
__device__ __forceinline__ void mma_f16(float c[4], const uint32_t a[4], const uint32_t b[2]) {
    asm volatile(
        "mma.sync.aligned.m16n8k16.row.col.f32.f16.f16.f32 "
        "{%0,%1,%2,%3}, {%4,%5,%6,%7}, {%8,%9}, {%0,%1,%2,%3};"
        : "+f"(c[0]), "+f"(c[1]), "+f"(c[2]), "+f"(c[3])
        : "r"(a[0]), "r"(a[1]), "r"(a[2]), "r"(a[3]), "r"(b[0]), "r"(b[1]));
}
__device__ __forceinline__ ull pk(float x, float y) {
    ull r; asm("mov.b64 %0,{%1,%2};" : "=l"(r) : "f"(x), "f"(y)); return r;
}
__device__ __forceinline__ float2 upk(ull v) {
    float2 f; asm("mov.b64 {%0,%1},%2;" : "=f"(f.x), "=f"(f.y) : "l"(v)); return f;
}
__device__ __forceinline__ void ffma2(ull &d, ull a, ull b) {
    asm volatile("fma.rn.f32x2 %0, %1, %2, %0;" : "+l"(d) : "l"(a), "l"(b));
}
__device__ __forceinline__ void lds2x64(ull &a, ull &b, uint32_t addr) {
    asm volatile("ld.shared.v2.b64 {%0,%1},[%2];" : "=l"(a), "=l"(b) : "r"(addr));
}
__device__ __forceinline__ float sigf(float x) { return 1.f/(1.f + __expf(-x)); }
__device__ __forceinline__ float tanhfast(float x) {
    float y; asm("tanh.approx.f32 %0,%1;" : "=f"(y) : "f"(x)); return y;
}

// ---------------------------------------------------------------------------
// Weight transpose+convert: in [K,N] fp32 -> out [N,K] fp16 (z-batched)
// ---------------------------------------------------------------------------
__global__ void wtrans(const float* __restrict__ in, __half* __restrict__ out,
                       int K, int N)
{
    __shared__ float t[32][33];
    const float* inz = in + (long)blockIdx.z*K*N;
    __half* outz = out + (long)blockIdx.z*K*N;
    int k0 = blockIdx.x*32, n0 = blockIdx.y*32;
    int tx = threadIdx.x, ty = threadIdx.y;
#pragma unroll
    for (int i=0;i<32;i+=8) {
        int k = k0+ty+i, n = n0+tx;
        t[ty+i][tx] = (k<K && n<N) ? inz[(long)k*N+n] : 0.f;
    }
    __syncthreads();
#pragma unroll
    for (int i=0;i<32;i+=8) {
        int n = n0+ty+i, k = k0+tx;
        if (n<N && k<K) outz[(long)n*K+k] = __float2half(t[tx][ty+i]);
    }
}

// ---------------------------------------------------------------------------
// x_h [m][b*256+s][128] -> xT_h [(m*64+b)*128 + d][256] (per (m,b): 128x256)
// grid (192, 4), block 256
// ---------------------------------------------------------------------------
__global__ void xtrans(const __half* __restrict__ xin, __half* __restrict__ xout)
{
    __shared__ __half sm[64][130];
    int mb = blockIdx.x;          // m*64+b
    int m = mb>>6, b = mb&63;
    int s0 = blockIdx.y*64;
    int tid = threadIdx.x;
    const __half* src = xin + ((long)m*BS + (long)b*Ss + s0)*128;
#pragma unroll
    for (int i=0;i<32;i++) {
        int idx = tid + i*256;          // 8192
        int s = idx>>7, d = idx&127;
        sm[s][d] = src[(long)s*128 + d];
    }
    __syncthreads();
    __half* dst = xout + (long)mb*128*Ss;
#pragma unroll
    for (int i=0;i<32;i++) {
        int idx = tid + i*256;
        int d = idx>>6, ss = idx&63;
        dst[(long)d*Ss + s0 + ss] = sm[ss][d];
    }
}

// ---------------------------------------------------------------------------
// TF32 GEMM (projections only). Writes fp16 output. 3-stage / sync fallback.
// ---------------------------------------------------------------------------
#define ASTR 36
#define BSTR 136
#define AWORDS (128*ASTR)
#define STG_WORDS (2*AWORDS)

template<bool PIPE, bool GATHER>
__launch_bounds__(256, 2)
__global__ void gemm_tf(const float* __restrict__ A, const float* __restrict__ B,
                        const float* __restrict__ bias, __half* __restrict__ C,
                        int M, int N, int K, int ldc,
                        const int* __restrict__ gidx)
{
    extern __shared__ uint32_t smp[];
    int m0 = blockIdx.y*128, n0 = blockIdx.x*128;
    int tid = threadIdx.x;
    int warp = tid>>5, lane = tid&31;
    int g = lane>>2, tig = lane&3;
    int wm = (warp&1)*64, wn = (warp>>1)*32;

    float c[4][4][4];
#pragma unroll
    for (int mt=0;mt<4;mt++)
#pragma unroll
        for (int nt=0;nt<4;nt++)
#pragma unroll
            for (int i=0;i<4;i++) c[mt][nt][i]=0.f;

    int lrow = tid>>3;
    int akq  = (tid&7)*4;
    const float* arp[4];
#pragma unroll
    for (int p=0;p<4;p++) {
        long grow = m0 + lrow + p*32;
        long r = GATHER ? (long)gidx[grow] : grow;
        arp[p] = A + r*(long)K;
    }
    int bnk = tid>>5;
    int bn4 = (tid&31)*4;

    auto load_tile = [&](int st, int k0) {
        uint32_t* As = smp + st*STG_WORDS;
        uint32_t* Bs = As + AWORDS;
        if (PIPE) {
#pragma unroll
            for (int p=0;p<4;p++) {
                int gk = k0 + akq;
                int bytes = (K - gk)*4; bytes = bytes<0?0:(bytes>16?16:bytes);
                const float* src = bytes ? (arp[p] + gk) : A;
                cpa16(s2u(&As[(lrow + p*32)*ASTR + akq]), src, bytes);
            }
#pragma unroll
            for (int p=0;p<4;p++) {
                int k = bnk + p*8;
                int ok = ((k0+k) < K) && ((n0+bn4) < N);
                const float* src = ok ? (B + (long)(k0+k)*N + n0 + bn4) : B;
                cpa16(s2u(&Bs[k*BSTR + bn4]), src, ok ? 16 : 0);
            }
        } else {
#pragma unroll
            for (int p=0;p<4;p++) {
                int gk = k0 + akq;
                uint4 u = {0u,0u,0u,0u};
                const float* ap = arp[p];
                if (gk+0 < K) u.x = __float_as_uint(ap[gk+0]);
                if (gk+1 < K) u.y = __float_as_uint(ap[gk+1]);
                if (gk+2 < K) u.z = __float_as_uint(ap[gk+2]);
                if (gk+3 < K) u.w = __float_as_uint(ap[gk+3]);
                *(uint4*)&As[(lrow + p*32)*ASTR + akq] = u;
            }
#pragma unroll
            for (int p=0;p<4;p++) {
                int k = bnk + p*8;
                uint4 u = {0u,0u,0u,0u};
                if ((k0+k) < K && (n0+bn4) < N) {
                    const float* bpr = B + (long)(k0+k)*N + n0 + bn4;
                    u.x = __float_as_uint(bpr[0]); u.y = __float_as_uint(bpr[1]);
                    u.z = __float_as_uint(bpr[2]); u.w = __float_as_uint(bpr[3]);
                }
                *(uint4*)&Bs[k*BSTR + bn4] = u;
            }
        }
    };
    auto compute = [&](int st) {
        const uint32_t* As = smp + st*STG_WORDS;
        const uint32_t* Bs = As + AWORDS;
#pragma unroll
        for (int ks=0;ks<4;ks++) {
            uint32_t a[4][4], b[4][2];
#pragma unroll
            for (int mt=0;mt<4;mt++) {
                int base = (wm + mt*16 + g)*ASTR + ks*8 + tig;
                a[mt][0] = As[base];
                a[mt][1] = As[base + 8*ASTR];
                a[mt][2] = As[base + 4];
                a[mt][3] = As[base + 8*ASTR + 4];
            }
#pragma unroll
            for (int nt=0;nt<4;nt++) {
                int base = (ks*8 + tig)*BSTR + wn + nt*8 + g;
                b[nt][0] = Bs[base];
                b[nt][1] = Bs[base + 4*BSTR];
            }
#pragma unroll
            for (int mt=0;mt<4;mt++)
#pragma unroll
                for (int nt=0;nt<4;nt++)
                    mma_tf32(c[mt][nt], a[mt], b[nt]);
        }
    };

    int ktn = (K+31)>>5;
    if (PIPE) {
        load_tile(0, 0);
        asm volatile("cp.async.commit_group;");
        if (ktn > 1) load_tile(1, 32);
        asm volatile("cp.async.commit_group;");
        for (int kt=0; kt<ktn; kt++) {
            asm volatile("cp.async.wait_group 1;");
            __syncthreads();
            if (kt+2 < ktn) load_tile((kt+2)%3, (kt+2)*32);
            asm volatile("cp.async.commit_group;");
            compute(kt%3);
            __syncthreads();
        }
    } else {
        for (int kt=0; kt<ktn; kt++) {
            load_tile(0, kt*32);
            __syncthreads();
            compute(0);
            __syncthreads();
        }
    }

#pragma unroll
    for (int mt=0;mt<4;mt++) {
        long m = m0 + wm + mt*16 + g;
#pragma unroll
        for (int nt=0;nt<4;nt++) {
            int n = n0 + wn + nt*8 + tig*2;
            if (n < N) {
                float bx = bias[n], by = bias[n+1];
                __half2 v0 = __floats2half2_rn(c[mt][nt][0]+bx, c[mt][nt][1]+by);
                __half2 v1 = __floats2half2_rn(c[mt][nt][2]+bx, c[mt][nt][3]+by);
                *(__half2*)&C[m*ldc + n] = v0;
                *(__half2*)&C[(m+8)*ldc + n] = v1;
            }
        }
    }
}

// ---------------------------------------------------------------------------
// FP16 NT GEMM: C_f32[z] = A_h[M,K] @ B_h[N,K]^T (+bias). Both K-contiguous.
// Block 128x128, BK=32 (2 k16 steps), 3-stage cp.async, warp tile 64x32.
// MODE 0: A + z*sA; MODE 1: A + (z>>1)*sA (GRU).
// ---------------------------------------------------------------------------
#define HSTR 20
#define HA_WORDS (128*HSTR)        // 2560
#define HSTG (2*HA_WORDS)          // 5120 words per stage

template<int MODE>
__launch_bounds__(256, 2)
__global__ void gemm_h(const __half* __restrict__ A, const __half* __restrict__ B,
                       const float* __restrict__ bias, float* __restrict__ C,
                       int M, int N, int K,
                       long sA, long sB, long sBias, long sC, int ldc)
{
    extern __shared__ uint32_t smp[];
    int z = blockIdx.z;
    const __half* Ab = A + (MODE==1 ? (long)(z>>1)*sA : (long)z*sA);
    const __half* Bp = B + (long)z*sB;
    const float* bp = bias + (long)z*sBias;
    float* Cb = C + (long)z*sC;

    int m0 = blockIdx.y*128, n0 = blockIdx.x*128;
    int tid = threadIdx.x;
    int warp = tid>>5, lane = tid&31;
    int g = lane>>2, tig = lane&3;
    int wm = (warp&1)*64, wn = (warp>>1)*32;

    float c[4][4][4];
#pragma unroll
    for (int mt=0;mt<4;mt++)
#pragma unroll
        for (int nt=0;nt<4;nt++)
#pragma unroll
            for (int i=0;i<4;i++) c[mt][nt][i]=0.f;

    int lrow = tid>>1;
    int lseg = (tid&1)*8;           // word offset 0 or 8 within 16-word row
    const __half* arow = Ab + (long)(m0+lrow)*K;
    const __half* brow = Bp + (long)(n0+lrow)*K;
    bool bok = (n0+lrow) < N;

    auto load_tile = [&](int st, int k0) {
        uint32_t* As = smp + st*HSTG;
        uint32_t* Bs = As + HA_WORDS;
        cpa16(s2u(&As[lrow*HSTR + lseg]),     arow + k0 + lseg*2,     16);
        cpa16(s2u(&As[lrow*HSTR + lseg + 4]), arow + k0 + lseg*2 + 8, 16);
        cpa16(s2u(&Bs[lrow*HSTR + lseg]),     bok ? (brow + k0 + lseg*2)     : brow, bok?16:0);
        cpa16(s2u(&Bs[lrow*HSTR + lseg + 4]), bok ? (brow + k0 + lseg*2 + 8) : brow, bok?16:0);
    };
    auto compute = [&](int st) {
        const uint32_t* As = smp + st*HSTG;
        const uint32_t* Bs = As + HA_WORDS;
#pragma unroll
        for (int ks=0;ks<2;ks++) {
            uint32_t a[4][4], b[4][2];
#pragma unroll
            for (int mt=0;mt<4;mt++) {
                int base = (wm + mt*16 + g)*HSTR + ks*8 + tig;
                a[mt][0] = As[base];
                a[mt][1] = As[base + 8*HSTR];
                a[mt][2] = As[base + 4];
                a[mt][3] = As[base + 8*HSTR + 4];
            }
#pragma unroll
            for (int nt=0;nt<4;nt++) {
                int base = (wn + nt*8 + g)*HSTR + ks*8 + tig;
                b[nt][0] = Bs[base];
                b[nt][1] = Bs[base + 4];
            }
#pragma unroll
            for (int mt=0;mt<4;mt++)
#pragma unroll
                for (int nt=0;nt<4;nt++)
                    mma_f16(c[mt][nt], a[mt], b[nt]);
        }
    };

    int ktn = K>>5;
    load_tile(0, 0);
    asm volatile("cp.async.commit_group;");
    if (ktn > 1) load_tile(1, 32);
    asm volatile("cp.async.commit_group;");
    for (int kt=0; kt<ktn; kt++) {
        asm volatile("cp.async.wait_group 1;");
        __syncthreads();
        if (kt+2 < ktn) load_tile((kt+2)%3, (kt+2)*32);
        asm volatile("cp.async.commit_group;");
        compute(kt%3);
        __syncthreads();
    }

#pragma unroll
    for (int mt=0;mt<4;mt++) {
        long m = m0 + wm + mt*16 + g;
#pragma unroll
        for (int nt=0;nt<4;nt++) {
            int n = n0 + wn + nt*8 + tig*2;
            if (n < N) {
                float bx = bp[n], by = bp[n+1];
                float2 v0, v1;
                v0.x = c[mt][nt][0]+bx; v0.y = c[mt][nt][1]+by;
                v1.x = c[mt][nt][2]+bx; v1.y = c[mt][nt][3]+by;
                *(float2*)&Cb[m*ldc + n] = v0;
                *(float2*)&Cb[(m+8)*ldc + n] = v1;
            }
        }
    }
}

// ---------------------------------------------------------------------------
// Fused fp16 QK^T + softmax -> P_h. Block 128x256, warp 64x64, K=128.
// grid (1, 2, 384): z = pair*64 + b.
// ---------------------------------------------------------------------------
#define QH_B (256*HSTR)            // 5120
#define QH_STG (HA_WORDS + QH_B)   // 7680 words per stage

__launch_bounds__(256, 1)
__global__ void qk_softmax_h(const __half* __restrict__ x, __half* __restrict__ P,
                             float scale)
{
    extern __shared__ uint32_t smp[];
    const int qtab[6]  = {0,0,1,1,2,2};
    const int kvtab[6] = {1,2,0,2,0,1};

    int z = blockIdx.z;
    int p = z>>6, b = z&63;
    const __half* Ab = x + ((long)qtab[p]*BS + (long)b*Ss)*128;
    const __half* Bp = x + ((long)kvtab[p]*BS + (long)b*Ss)*128;
    __half* Cb = P + (long)z*Ss*Ss;
    int m0 = blockIdx.y*128;
    int tid = threadIdx.x;
    int warp = tid>>5, lane = tid&31;
    int g = lane>>2, tig = lane&3;
    int wm = (warp&1)*64, wn = (warp>>1)*64;

    float c[4][8][4];
#pragma unroll
    for (int mt=0;mt<4;mt++)
#pragma unroll
        for (int nt=0;nt<8;nt++)
#pragma unroll
            for (int i=0;i<4;i++) c[mt][nt][i]=0.f;

    int lrow = tid>>1;
    int lseg = (tid&1)*8;
    const __half* arow = Ab + (long)(m0+lrow)*128;
    const __half* brow = Bp + (long)tid*128;

    auto load_tile = [&](int st, int k0) {
        uint32_t* As = smp + st*QH_STG;
        uint32_t* Bs = As + HA_WORDS;
        cpa16(s2u(&As[lrow*HSTR + lseg]),     arow + k0 + lseg*2,     16);
        cpa16(s2u(&As[lrow*HSTR + lseg + 4]), arow + k0 + lseg*2 + 8, 16);
#pragma unroll
        for (int h=0;h<4;h++)
            cpa16(s2u(&Bs[tid*HSTR + h*4]), brow + k0 + h*8, 16);
    };
    auto compute = [&](int st) {
        const uint32_t* As = smp + st*QH_STG;
        const uint32_t* Bs = As + HA_WORDS;
#pragma unroll
        for (int ks=0;ks<2;ks++) {
            uint32_t a[4][4], bb[8][2];
#pragma unroll
            for (int mt=0;mt<4;mt++) {
                int base = (wm + mt*16 + g)*HSTR + ks*8 + tig;
                a[mt][0] = As[base];
                a[mt][1] = As[base + 8*HSTR];
                a[mt][2] = As[base + 4];
                a[mt][3] = As[base + 8*HSTR + 4];
            }
#pragma unroll
            for (int nt=0;nt<8;nt++) {
                int base = (wn + nt*8 + g)*HSTR + ks*8 + tig;
                bb[nt][0] = Bs[base];
                bb[nt][1] = Bs[base + 4];
            }
#pragma unroll
            for (int mt=0;mt<4;mt++)
#pragma unroll
                for (int nt=0;nt<8;nt++)
                    mma_f16(c[mt][nt], a[mt], bb[nt]);
        }
    };

    load_tile(0, 0);
    asm volatile("cp.async.commit_group;");
    load_tile(1, 32);
    asm volatile("cp.async.commit_group;");
    for (int kt=0; kt<4; kt++) {
        asm volatile("cp.async.wait_group 1;");
        __syncthreads();
        if (kt+2 < 4) load_tile((kt+2)%3, (kt+2)*32);
        asm volatile("cp.async.commit_group;");
        compute(kt%3);
        __syncthreads();
    }

    // softmax over 256 cols
#pragma unroll
    for (int mt=0;mt<4;mt++)
#pragma unroll
        for (int nt=0;nt<8;nt++)
#pragma unroll
            for (int i=0;i<4;i++) c[mt][nt][i] *= scale;

    float* red = (float*)smp;
    int wcol = warp>>1;
    float rmax[4][2], rinv[4][2];

#pragma unroll
    for (int mt=0;mt<4;mt++)
#pragma unroll
        for (int h=0;h<2;h++) {
            float m = -1e30f;
#pragma unroll
            for (int nt=0;nt<8;nt++)
                m = fmaxf(m, fmaxf(c[mt][nt][2*h], c[mt][nt][2*h+1]));
            m = fmaxf(m, __shfl_xor_sync(0xffffffffu, m, 1));
            m = fmaxf(m, __shfl_xor_sync(0xffffffffu, m, 2));
            if (tig == 0) red[(wm + mt*16 + g + h*8)*4 + wcol] = m;
        }
    __syncthreads();
#pragma unroll
    for (int mt=0;mt<4;mt++)
#pragma unroll
        for (int h=0;h<2;h++) {
            int r = wm + mt*16 + g + h*8;
            rmax[mt][h] = fmaxf(fmaxf(red[r*4], red[r*4+1]),
                                fmaxf(red[r*4+2], red[r*4+3]));
        }
    __syncthreads();
#pragma unroll
    for (int mt=0;mt<4;mt++)
#pragma unroll
        for (int h=0;h<2;h++) {
            float s = 0.f;
#pragma unroll
            for (int nt=0;nt<8;nt++) {
                float e0 = __expf(c[mt][nt][2*h]   - rmax[mt][h]);
                float e1 = __expf(c[mt][nt][2*h+1] - rmax[mt][h]);
                c[mt][nt][2*h]   = e0;
                c[mt][nt][2*h+1] = e1;
                s += e0 + e1;
            }
            s += __shfl_xor_sync(0xffffffffu, s, 1);
            s += __shfl_xor_sync(0xffffffffu, s, 2);
            if (tig == 0) red[(wm + mt*16 + g + h*8)*4 + wcol] = s;
        }
    __syncthreads();
#pragma unroll
    for (int mt=0;mt<4;mt++)
#pragma unroll
        for (int h=0;h<2;h++) {
            int r = wm + mt*16 + g + h*8;
            rinv[mt][h] = 1.f/(red[r*4] + red[r*4+1] + red[r*4+2] + red[r*4+3]);
        }
#pragma unroll
    for (int mt=0;mt<4;mt++)
#pragma unroll
        for (int h=0;h<2;h++) {
            long row = m0 + wm + mt*16 + g + h*8;
#pragma unroll
            for (int nt=0;nt<8;nt++) {
                int col = wn + nt*8 + tig*2;
                __half2 v = __floats2half2_rn(c[mt][nt][2*h]   * rinv[mt][h],
                                              c[mt][nt][2*h+1] * rinv[mt][h]);
                *(__half2*)&Cb[row*256 + col] = v;
            }
        }
}

// ---------------------------------------------------------------------------
// Merged PV (fp16): tstep[:, q*128:] += sum over 2 kv of P_h @ xT_h^T.
// grid (1, 2, 192): z = q*64 + b. Also writes tstep_h.
// ---------------------------------------------------------------------------
__launch_bounds__(256, 2)
__global__ void pv_h(const __half* __restrict__ P, const __half* __restrict__ xT,
                     float* __restrict__ tstep, __half* __restrict__ tstep_h)
{
    extern __shared__ uint32_t smp[];
    const int kvtab[6] = {1,2,0,2,0,1};
    int z = blockIdx.z;
    int qq = z>>6, b = z&63;
    float* Cb = tstep + (long)qq*128 + (long)b*Ss*384;
    __half* Ch = tstep_h + (long)qq*128 + (long)b*Ss*384;

    int m0 = blockIdx.y*128;
    int tid = threadIdx.x;
    int warp = tid>>5, lane = tid&31;
    int g = lane>>2, tig = lane&3;
    int wm = (warp&1)*64, wn = (warp>>1)*32;

    float c[4][4][4];
#pragma unroll
    for (int mt=0;mt<4;mt++)
#pragma unroll
        for (int nt=0;nt<4;nt++)
#pragma unroll
            for (int i=0;i<4;i++) c[mt][nt][i]=0.f;

    int lrow = tid>>1;
    int lseg = (tid&1)*8;
    const __half *arow = nullptr, *brow = nullptr;

    auto load_tile = [&](int st, int k0) {
        uint32_t* As = smp + st*HSTG;
        uint32_t* Bs = As + HA_WORDS;
        cpa16(s2u(&As[lrow*HSTR + lseg]),     arow + k0 + lseg*2,     16);
        cpa16(s2u(&As[lrow*HSTR + lseg + 4]), arow + k0 + lseg*2 + 8, 16);
        cpa16(s2u(&Bs[lrow*HSTR + lseg]),     brow + k0 + lseg*2,     16);
        cpa16(s2u(&Bs[lrow*HSTR + lseg + 4]), brow + k0 + lseg*2 + 8, 16);
    };
    auto compute = [&](int st) {
        const uint32_t* As = smp + st*HSTG;
        const uint32_t* Bs = As + HA_WORDS;
#pragma unroll
        for (int ks=0;ks<2;ks++) {
            uint32_t a[4][4], bb[4][2];
#pragma unroll
            for (int mt=0;mt<4;mt++) {
                int base = (wm + mt*16 + g)*HSTR + ks*8 + tig;
                a[mt][0] = As[base];
                a[mt][1] = As[base + 8*HSTR];
                a[mt][2] = As[base + 4];
                a[mt][3] = As[base + 8*HSTR + 4];
            }
#pragma unroll
            for (int nt=0;nt<4;nt++) {
                int base = (wn + nt*8 + g)*HSTR + ks*8 + tig;
                bb[nt][0] = Bs[base];
                bb[nt][1] = Bs[base + 4];
            }
#pragma unroll
            for (int mt=0;mt<4;mt++)
#pragma unroll
                for (int nt=0;nt<4;nt++)
                    mma_f16(c[mt][nt], a[mt], bb[nt]);
        }
    };

    for (int seg=0; seg<2; seg++) {
        int p = 2*qq + seg;
        arow = P + ((long)p*64 + b)*(long)Ss*Ss + (long)(m0+lrow)*Ss;
        brow = xT + ((long)kvtab[p]*64 + b)*128l*Ss + (long)lrow*Ss;
        if (seg) {
            asm volatile("cp.async.wait_group 0;");
            __syncthreads();
        }
        load_tile(0, 0);
        asm volatile("cp.async.commit_group;");
        load_tile(1, 32);
        asm volatile("cp.async.commit_group;");
        for (int kt=0; kt<8; kt++) {
            asm volatile("cp.async.wait_group 1;");
            __syncthreads();
            if (kt+2 < 8) load_tile((kt+2)%3, (kt+2)*32);
            asm volatile("cp.async.commit_group;");
            compute(kt%3);
            __syncthreads();
        }
    }

#pragma unroll
    for (int mt=0;mt<4;mt++) {
        long m = m0 + wm + mt*16 + g;
#pragma unroll
        for (int nt=0;nt<4;nt++) {
            int n = wn + nt*8 + tig*2;
            float2 o0 = *(const float2*)&Cb[m*384 + n];
            float2 o1 = *(const float2*)&Cb[(m+8)*384 + n];
            float2 v0, v1;
            v0.x = c[mt][nt][0]+o0.x; v0.y = c[mt][nt][1]+o0.y;
            v1.x = c[mt][nt][2]+o1.x; v1.y = c[mt][nt][3]+o1.y;
            *(float2*)&Cb[m*384 + n] = v0;
            *(float2*)&Cb[(m+8)*384 + n] = v1;
            *(__half2*)&Ch[m*384 + n] = __floats2half2_rn(v0.x, v0.y);
            *(__half2*)&Ch[(m+8)*384 + n] = __floats2half2_rn(v1.x, v1.y);
        }
    }
}

// ---------------------------------------------------------------------------
// biGRU: writes x_h (fp16) and fp32 tstep slab.
// ---------------------------------------------------------------------------
__launch_bounds__(192, 3)
__global__ void gru_rec(const float* __restrict__ xg_all, const float* __restrict__ Wh,
                        const float* __restrict__ bh, __half* __restrict__ x_h,
                        float* __restrict__ tstep)
{
    int bx = blockIdx.x;
    int m = bx>>7, d = (bx>>6)&1, b = bx&63, md = m*2+d;
    int j = threadIdx.x;
    ull w2[32];
#pragma unroll
    for (int q=0;q<32;q++)
        w2[q] = pk(Wh[((long)md*64 + 2*q)*192 + j], Wh[((long)md*64 + 2*q+1)*192 + j]);
    float bhj = bh[md*192 + j];
    __shared__ alignas(16) float h_s[64];
    __shared__ float pre_s[192], xn_s[64];
    uint32_t hsa = s2u(h_s);
    if (j<64) h_s[j]=0.f;
    const float* xg = xg_all + ((long)md*BS + (long)b*Ss)*192;
    for (int t=0;t<Ss;t++) {
        int s = d ? (Ss-1-t) : t;
        __syncthreads();
        ull a0 = pk(bhj, 0.f), a1 = pk(0.f, 0.f);
#pragma unroll
        for (int q=0;q<16;q++) {
            ull h0,h1; lds2x64(h0,h1, hsa + q*16);
            ffma2(a0, h0, w2[2*q]);
            ffma2(a1, h1, w2[2*q+1]);
        }
        float2 f0 = upk(a0), f1 = upk(a1);
        float acc = f0.x + f0.y + f1.x + f1.y;
        float xgv = xg[(long)s*192 + j];
        if (j<128) pre_s[j] = acc + xgv;
        else { pre_s[j] = acc; xn_s[j-128] = xgv; }
        __syncthreads();
        if (j<64) {
            float r = sigf(pre_s[j]);
            float zg = sigf(pre_s[64+j]);
            float n = tanhfast(xn_s[j] + r*pre_s[128+j]);
            float hn = (1.f-zg)*n + zg*h_s[j];
            h_s[j] = hn;
            long row = (long)b*Ss + s;
            x_h[((long)m*BS + row)*128 + d*64 + j] = __float2half(hn);
            tstep[row*384 + m*128 + d*64 + j] = hn;
        }
    }
}

// ---------------------------------------------------------------------------
// biLSTM: writes sf_h fp16.
// ---------------------------------------------------------------------------
__launch_bounds__(512, 1)
__global__ void lstm_rec(const float* __restrict__ xg_all, const float* __restrict__ Wh,
                         const float* __restrict__ bh, __half* __restrict__ sf_h)
{
    extern __shared__ unsigned char smraw[];
    ull*   Wlo2  = (ull*)smraw;
    float* h_s   = (float*)(smraw + 16*512*8);
    float* pre_s = (float*)(smraw + 16*512*8 + 512);
    int bx = blockIdx.x, d = bx>>6, b = bx&63;
    int j = threadIdx.x;
    const float* Whd = Wh + (long)d*128*512;
    ull w2[48];
#pragma unroll
    for (int q=0;q<48;q++)
        w2[q] = pk(Whd[(long)(2*q)*512 + j], Whd[(long)(2*q+1)*512 + j]);
    for (int q=0;q<16;q++)
        Wlo2[q*512 + j] = pk(Whd[(long)(96+2*q)*512 + j], Whd[(long)(97+2*q)*512 + j]);
    float bhj = bh[d*512 + j];
    float c = 0.f;
    if (j<128) h_s[j]=0.f;
    uint32_t hsa = s2u(h_s);
    const float* xg = xg_all + ((long)d*BS + (long)b*Ss)*512;
    for (int t=0;t<Ss;t++) {
        int s = d ? (Ss-1-t) : t;
        __syncthreads();
        ull a0 = pk(bhj, 0.f), a1 = pk(0.f, 0.f);
#pragma unroll
        for (int q=0;q<24;q++) {
            ull h0,h1; lds2x64(h0,h1, hsa + q*16);
            ffma2(a0, h0, w2[2*q]);
            ffma2(a1, h1, w2[2*q+1]);
        }
#pragma unroll
        for (int q=0;q<8;q++) {
            ull h0,h1; lds2x64(h0,h1, hsa + 384 + q*16);
            ffma2(a0, h0, Wlo2[(2*q)*512 + j]);
            ffma2(a1, h1, Wlo2[(2*q+1)*512 + j]);
        }
        float2 f0 = upk(a0), f1 = upk(a1);
        float acc = f0.x + f0.y + f1.x + f1.y + xg[(long)s*512 + j];
        pre_s[j] = acc;
        __syncthreads();
        if (j<128) {
            float ig = pre_s[j], fg = pre_s[128+j], gg = pre_s[256+j], og = pre_s[384+j];
            c = sigf(fg)*c + sigf(ig)*tanhfast(gg);
            float h = sigf(og)*tanhfast(c);
            h_s[j] = h;
            sf_h[((long)b*Ss + s)*256 + d*128 + j] = __float2half(h);
        }
    }
}

// ---------------------------------------------------------------------------
__launch_bounds__(384, 1)
__global__ void rgn_rec(const float* __restrict__ xg_all, const float* __restrict__ Wh,
                        const float* __restrict__ state0, const float* __restrict__ state1,
                        float* __restrict__ outbuf)
{
    __shared__ alignas(16) float h_s[128];
    __shared__ float pre_s[384], xn_s[128];
    int bx = blockIdx.x, kk = bx>>6, b = bx&63;
    int j = threadIdx.x;
    const float* Whd = Wh + (long)kk*128*384;
    ull w2[64];
#pragma unroll
    for (int q=0;q<64;q++)
        w2[q] = pk(Whd[(long)(2*q)*384 + j], Whd[(long)(2*q+1)*384 + j]);
    if (j<128) h_s[j] = (kk==0?state0:state1)[b*128 + j];
    uint32_t hsa = s2u(h_s);
    const float* xg = xg_all + ((long)kk*BS + (long)b*Ss)*384;
    for (int t=0;t<Ss;t++) {
        int s = kk ? (Ss-1-t) : t;
        __syncthreads();
        ull a0 = pk(0.f, 0.f), a1 = pk(0.f, 0.f);
#pragma unroll
        for (int q=0;q<32;q++) {
            ull h0,h1; lds2x64(h0,h1, hsa + q*16);
            ffma2(a0, h0, w2[2*q]);
            ffma2(a1, h1, w2[2*q+1]);
        }
        float2 f0 = upk(a0), f1 = upk(a1);
        float acc = f0.x + f0.y + f1.x + f1.y;
        float xgv = xg[(long)s*384 + j];
        if (j<256) pre_s[j] = acc + xgv;
        else { pre_s[j] = acc; xn_s[j-256] = xgv; }
        __syncthreads();
        if (j<128) {
            float r = sigf(pre_s[j]);
            float z = sigf(pre_s[128+j]);
            float n = tanhfast(xn_s[j] + r*pre_s[256+j]);
            h_s[j] = (1.f-z)*n + z*h_s[j];
        }
    }
    __syncthreads();
    if (j<128) outbuf[((long)kk*64 + b)*128 + j] = h_s[j];
}

__launch_bounds__(32)
__global__ void final_fc(const float* __restrict__ outbuf,
                         const float* __restrict__ fc1W, const float* __restrict__ fc1b,
                         const float* __restrict__ fc2W, const float* __restrict__ fc2b,
                         float* __restrict__ out)
{
    int b = blockIdx.x, t = threadIdx.x;
    float acc = fc1b[t];
    for (int k=0;k<128;k++) {
        float x = outbuf[b*128+k] + outbuf[64*128 + b*128 + k];
        acc += x * fc1W[k*32 + t];
    }
    float h = acc > 0.f ? acc : 0.01f*acc;
    float v = h * fc2W[t];
#pragma unroll
    for (int o=16;o;o>>=1) v += __shfl_xor_sync(0xffffffffu, v, o);
    if (t==0) out[b] = v + fc2b[0];
}

extern "C" void kernel_launch(void* const* d_in, const int* in_sizes, int n_in,
                              void* d_out, int out_size)
{
    (void)in_sizes; (void)n_in; (void)out_size;
    const int*   sentences = (const int*)  d_in[0];
    const float* acoustic  = (const float*)d_in[1];
    const float* video     = (const float*)d_in[2];
    const float* state0    = (const float*)d_in[3];
    const float* state1    = (const float*)d_in[4];
    const float* emb       = (const float*)d_in[5];
    const float* proj_l_W  = (const float*)d_in[6];
    const float* proj_l_b  = (const float*)d_in[7];
    const float* proj_a_W  = (const float*)d_in[8];
    const float* proj_a_b  = (const float*)d_in[9];
    const float* proj_v_W  = (const float*)d_in[10];
    const float* proj_v_b  = (const float*)d_in[11];
    const float* gru_Wi    = (const float*)d_in[12];
    const float* gru_Wh    = (const float*)d_in[13];
    const float* gru_bi    = (const float*)d_in[14];
    const float* gru_bh    = (const float*)d_in[15];
    const float* lstm_Wi   = (const float*)d_in[16];
    const float* lstm_Wh   = (const float*)d_in[17];
    const float* lstm_bi   = (const float*)d_in[18];
    const float* lstm_bh   = (const float*)d_in[19];
    const float* rgn_Wx    = (const float*)d_in[20];
    const float* rgn_Wh    = (const float*)d_in[21];
    const float* rgn_b     = (const float*)d_in[22];
    const float* fc1_W     = (const float*)d_in[23];
    const float* fc1_b     = (const float*)d_in[24];
    const float* fc2_W     = (const float*)d_in[25];
    const float* fc2_b     = (const float*)d_in[26];
    float* out = (float*)d_out;

    float *xg_gru,*tstep,*xg_lstm,*xg_rgn,*rgn_out;
    __half *seq_h,*x_h,*xT_h,*P_h,*tstep_h,*sf_h,*WT_h;
    cudaGetSymbolAddress((void**)&xg_gru, g_xg_gru);
    cudaGetSymbolAddress((void**)&tstep, g_tstep);
    cudaGetSymbolAddress((void**)&xg_lstm, g_xg_lstm);
    cudaGetSymbolAddress((void**)&xg_rgn, g_xg_rgn);
    cudaGetSymbolAddress((void**)&rgn_out, g_rgn_out);
    cudaGetSymbolAddress((void**)&seq_h, g_seq_h);
    cudaGetSymbolAddress((void**)&x_h, g_x_h);
    cudaGetSymbolAddress((void**)&xT_h, g_xT_h);
    cudaGetSymbolAddress((void**)&P_h, g_P_h);
    cudaGetSymbolAddress((void**)&tstep_h, g_tstep_h);
    cudaGetSymbolAddress((void**)&sf_h, g_sf_h);
    cudaGetSymbolAddress((void**)&WT_h, g_WT_h);
    __half* gruT = WT_h;
    __half* lstmT = WT_h + 6*192*128;
    __half* rgnT = lstmT + 2l*512*384;

    const size_t shm_tf3 = 3u*STG_WORDS*4u;  // 110592
    const size_t shm_tf1 = 1u*STG_WORDS*4u;  // 36864
    const size_t shm_h   = 3u*HSTG*4u;       // 61440
    const size_t shm_qk  = 3u*QH_STG*4u;     // 92160
    cudaFuncSetAttribute(gemm_tf<true,true>,   cudaFuncAttributeMaxDynamicSharedMemorySize, (int)shm_tf3);
    cudaFuncSetAttribute(gemm_tf<false,false>, cudaFuncAttributeMaxDynamicSharedMemorySize, (int)shm_tf1);
    cudaFuncSetAttribute(gemm_h<0>, cudaFuncAttributeMaxDynamicSharedMemorySize, (int)shm_h);
    cudaFuncSetAttribute(gemm_h<1>, cudaFuncAttributeMaxDynamicSharedMemorySize, (int)shm_h);
    cudaFuncSetAttribute(qk_softmax_h, cudaFuncAttributeMaxDynamicSharedMemorySize, (int)shm_qk);
    cudaFuncSetAttribute(pv_h, cudaFuncAttributeMaxDynamicSharedMemorySize, (int)shm_h);
    cudaFuncSetAttribute(lstm_rec, cudaFuncAttributeMaxDynamicSharedMemorySize, 72*1024);

    // weight transposes (fp32 -> fp16 [N,K])
    wtrans<<<dim3(4, 6, 6), dim3(32,8)>>>(gru_Wi, gruT, 128, 192);
    wtrans<<<dim3(12, 16, 2), dim3(32,8)>>>(lstm_Wi, lstmT, 384, 512);
    wtrans<<<dim3(8, 12, 2), dim3(32,8)>>>(rgn_Wx, rgnT, 256, 384);

    // modality projections -> seq_h (fp16)
    gemm_tf<true,true><<<dim3(1, BS/128, 1), 256, shm_tf3>>>(
        emb, proj_l_W, proj_l_b, seq_h, BS, 128, DL, 128, sentences);
    gemm_tf<false,false><<<dim3(1, BS/128, 1), 256, shm_tf1>>>(
        acoustic, proj_a_W, proj_a_b, seq_h + 1l*BS*DH, BS, 128, DA, 128, nullptr);
    gemm_tf<false,false><<<dim3(1, BS/128, 1), 256, shm_tf1>>>(
        video, proj_v_W, proj_v_b, seq_h + 2l*BS*DH, BS, 128, DV, 128, nullptr);

    // GRU input projections (fp16, z=6)
    gemm_h<1><<<dim3(2, BS/128, 6), 256, shm_h>>>(
        seq_h, gruT, gru_bi, xg_gru, BS, 192, 128,
        (long)BS*DH, 192l*128, 192, (long)BS*192, 192);

    gru_rec<<<3*2*64, 192>>>(xg_gru, gru_Wh, gru_bh, x_h, tstep);
    xtrans<<<dim3(192, 4), 256>>>(x_h, xT_h);

    // JCAF
    const float scale = 0.08838834764831845f;
    qk_softmax_h<<<dim3(1, 2, 384), 256, shm_qk>>>(x_h, P_h, scale);
    pv_h<<<dim3(1, 2, 192), 256, shm_h>>>(P_h, xT_h, tstep, tstep_h);

    // LSTM input projections (fp16, z=2, shared A)
    gemm_h<0><<<dim3(4, BS/128, 2), 256, shm_h>>>(
        tstep_h, lstmT, lstm_bi, xg_lstm, BS, 512, 384,
        0, 512l*384, 512, (long)BS*512, 512);

    lstm_rec<<<2*64, 512, 16*512*8 + 512 + 2048>>>(xg_lstm, lstm_Wh, lstm_bh, sf_h);

    // RGN input projections (fp16, z=2, shared A)
    gemm_h<0><<<dim3(3, BS/128, 2), 256, shm_h>>>(
        sf_h, rgnT, rgn_b, xg_rgn, BS, 384, 256,
        0, 384l*256, 384, (long)BS*384, 384);

    rgn_rec<<<2*64, 384>>>(xg_rgn, rgn_Wh, state0, state1, rgn_out);

    final_fc<<<Bb, 32>>>(rgn_out, fc1_W, fc1_b, fc2_W, fc2_b, out);
}

// round 9
// speedup vs baseline: 1.1634x; 1.0598x over previous
#include <cuda_runtime.h>
#include <cuda_fp16.h>
#include <math.h>
#include <stdint.h>

#define Bb 64
#define Ss 256
#define BS (Bb*Ss)
#define DL 300
#define DA 74
#define DV 35
#define DH 128

// fp32 scratch
__device__ float g_xg_gru[6u*BS*192];
__device__ float g_tstep[(unsigned)BS*384];
__device__ float g_xg_lstm[2u*BS*512];
__device__ float g_xg_rgn[2u*BS*384];
__device__ float g_rgn_out[2u*Bb*128];
// fp16 scratch
__device__ __half g_seq_h[3u*BS*DH];
__device__ __half g_x_h[3u*BS*DH];
__device__ __half g_xT_h[3u*(unsigned)Bb*128*Ss];
__device__ __half g_P_h[6u*(unsigned)Bb*Ss*Ss];
__device__ __half g_tstep_h[(unsigned)BS*384];
__device__ __half g_sf_h[(unsigned)BS*256];
__device__ __half g_ac_h[(unsigned)BS*96];
__device__ __half g_vid_h[(unsigned)BS*64];
__device__ __half g_WT_h[757760];

typedef unsigned long long ull;

__device__ __forceinline__ uint32_t s2u(const void* p) {
    return (uint32_t)__cvta_generic_to_shared(p);
}
__device__ __forceinline__ void cpa16(uint32_t dst, const void* src, int bytes) {
    asm volatile("cp.async.cg.shared.global [%0], [%1], 16, %2;"
                 :: "r"(dst), "l"(src), "r"(bytes));
}
__device__ __forceinline__ void mma_tf32(float c[4], const uint32_t a[4], const uint32_t b[2]) {
    asm volatile(
        "mma.sync.aligned.m16n8k8.row.col.f32.tf32.tf32.f32 "
        "{%0,%1,%2,%3}, {%4,%5,%6,%7}, {%8,%9}, {%0,%1,%2,%3};"
        : "+f"(c[0]), "+f"(c[1]), "+f"(c[2]), "+f"(c[3])
        : "r"(a[0]), "r"(a[1]), "r"(a[2]), "r"(a[3]), "r"(b[0]), "r"(b[1]));
}
__device__ __forceinline__ void mma_f16(float c[4], const uint32_t a[4], const uint32_t b[2]) {
    asm volatile(
        "mma.sync.aligned.m16n8k16.row.col.f32.f16.f16.f32 "
        "{%0,%1,%2,%3}, {%4,%5,%6,%7}, {%8,%9}, {%0,%1,%2,%3};"
        : "+f"(c[0]), "+f"(c[1]), "+f"(c[2]), "+f"(c[3])
        : "r"(a[0]), "r"(a[1]), "r"(a[2]), "r"(a[3]), "r"(b[0]), "r"(b[1]));
}
__device__ __forceinline__ ull pk(float x, float y) {
    ull r; asm("mov.b64 %0,{%1,%2};" : "=l"(r) : "f"(x), "f"(y)); return r;
}
__device__ __forceinline__ float2 upk(ull v) {
    float2 f; asm("mov.b64 {%0,%1},%2;" : "=f"(f.x), "=f"(f.y) : "l"(v)); return f;
}
__device__ __forceinline__ void ffma2(ull &d, ull a, ull b) {
    asm volatile("fma.rn.f32x2 %0, %1, %2, %0;" : "+l"(d) : "l"(a), "l"(b));
}
__device__ __forceinline__ void lds2x64(ull &a, ull &b, uint32_t addr) {
    asm volatile("ld.shared.v2.b64 {%0,%1},[%2];" : "=l"(a), "=l"(b) : "r"(addr));
}
__device__ __forceinline__ float sigf(float x) { return 1.f/(1.f + __expf(-x)); }
__device__ __forceinline__ float tanhfast(float x) {
    float y; asm("tanh.approx.f32 %0,%1;" : "=f"(y) : "f"(x)); return y;
}

// ---------------------------------------------------------------------------
// Weight transpose+convert: in [K,N] fp32 -> out [N,KP] fp16, zero-pad K..KP
// ---------------------------------------------------------------------------
__global__ void wtrans(const float* __restrict__ in, __half* __restrict__ out,
                       int K, int N, int KP)
{
    __shared__ float t[32][33];
    const float* inz = in + (long)blockIdx.z*K*N;
    __half* outz = out + (long)blockIdx.z*N*KP;
    int k0 = blockIdx.x*32, n0 = blockIdx.y*32;
    int tx = threadIdx.x, ty = threadIdx.y;
#pragma unroll
    for (int i=0;i<32;i+=8) {
        int k = k0+ty+i, n = n0+tx;
        t[ty+i][tx] = (k<K && n<N) ? inz[(long)k*N+n] : 0.f;
    }
    __syncthreads();
#pragma unroll
    for (int i=0;i<32;i+=8) {
        int n = n0+ty+i, k = k0+tx;
        if (n<N && k<KP) outz[(long)n*KP+k] = __float2half(t[tx][ty+i]);
    }
}

// elementwise fp32 [M,K] -> fp16 [M,KP] zero-padded
__global__ void conv_pad(const float* __restrict__ in, __half* __restrict__ out,
                         int M, int K, int KP)
{
    long tot = (long)M*KP;
    for (long i = (long)blockIdx.x*blockDim.x + threadIdx.x; i < tot;
         i += (long)gridDim.x*blockDim.x) {
        long row = i/KP; int k = (int)(i - row*KP);
        out[i] = (k<K) ? __float2half(in[row*K + k]) : __float2half(0.f);
    }
}

// ---------------------------------------------------------------------------
// x_h -> xT_h transpose
// ---------------------------------------------------------------------------
__global__ void xtrans(const __half* __restrict__ xin, __half* __restrict__ xout)
{
    __shared__ __half sm[64][130];
    int mb = blockIdx.x;
    int m = mb>>6, b = mb&63;
    int s0 = blockIdx.y*64;
    int tid = threadIdx.x;
    const __half* src = xin + ((long)m*BS + (long)b*Ss + s0)*128;
#pragma unroll
    for (int i=0;i<32;i++) {
        int idx = tid + i*256;
        int s = idx>>7, d = idx&127;
        sm[s][d] = src[(long)s*128 + d];
    }
    __syncthreads();
    __half* dst = xout + (long)mb*128*Ss;
#pragma unroll
    for (int i=0;i<32;i++) {
        int idx = tid + i*256;
        int d = idx>>6, ss = idx&63;
        dst[(long)d*Ss + s0 + ss] = sm[ss][d];
    }
}

// ---------------------------------------------------------------------------
// TF32 GEMM (embedding projection only). fp16 output, 3-stage pipeline.
// ---------------------------------------------------------------------------
#define ASTR 36
#define BSTR 136
#define AWORDS (128*ASTR)
#define STG_WORDS (2*AWORDS)

__launch_bounds__(256, 2)
__global__ void gemm_tf(const float* __restrict__ A, const float* __restrict__ W,
                        const float* __restrict__ bias, __half* __restrict__ C,
                        int M, int N, int K, int ldc,
                        const int* __restrict__ gidx)
{
    extern __shared__ uint32_t smp[];
    int m0 = blockIdx.y*128, n0 = blockIdx.x*128;
    int tid = threadIdx.x;
    int warp = tid>>5, lane = tid&31;
    int g = lane>>2, tig = lane&3;
    int wm = (warp&1)*64, wn = (warp>>1)*32;

    float c[4][4][4];
#pragma unroll
    for (int mt=0;mt<4;mt++)
#pragma unroll
        for (int nt=0;nt<4;nt++)
#pragma unroll
            for (int i=0;i<4;i++) c[mt][nt][i]=0.f;

    int lrow = tid>>3;
    int akq  = (tid&7)*4;
    const float* arp[4];
#pragma unroll
    for (int p=0;p<4;p++)
        arp[p] = A + (long)gidx[m0 + lrow + p*32]*(long)K;
    int bnk = tid>>5;
    int bn4 = (tid&31)*4;

    auto load_tile = [&](int st, int k0) {
        uint32_t* As = smp + st*STG_WORDS;
        uint32_t* Bs = As + AWORDS;
#pragma unroll
        for (int p=0;p<4;p++) {
            int gk = k0 + akq;
            int bytes = (K - gk)*4; bytes = bytes<0?0:(bytes>16?16:bytes);
            const float* src = bytes ? (arp[p] + gk) : A;
            cpa16(s2u(&As[(lrow + p*32)*ASTR + akq]), src, bytes);
        }
#pragma unroll
        for (int p=0;p<4;p++) {
            int k = bnk + p*8;
            int ok = ((k0+k) < K) && ((n0+bn4) < N);
            const float* src = ok ? (W + (long)(k0+k)*N + n0 + bn4) : W;
            cpa16(s2u(&Bs[k*BSTR + bn4]), src, ok ? 16 : 0);
        }
    };
    auto compute = [&](int st) {
        const uint32_t* As = smp + st*STG_WORDS;
        const uint32_t* Bs = As + AWORDS;
#pragma unroll
        for (int ks=0;ks<4;ks++) {
            uint32_t a[4][4], b[4][2];
#pragma unroll
            for (int mt=0;mt<4;mt++) {
                int base = (wm + mt*16 + g)*ASTR + ks*8 + tig;
                a[mt][0] = As[base];
                a[mt][1] = As[base + 8*ASTR];
                a[mt][2] = As[base + 4];
                a[mt][3] = As[base + 8*ASTR + 4];
            }
#pragma unroll
            for (int nt=0;nt<4;nt++) {
                int base = (ks*8 + tig)*BSTR + wn + nt*8 + g;
                b[nt][0] = Bs[base];
                b[nt][1] = Bs[base + 4*BSTR];
            }
#pragma unroll
            for (int mt=0;mt<4;mt++)
#pragma unroll
                for (int nt=0;nt<4;nt++)
                    mma_tf32(c[mt][nt], a[mt], b[nt]);
        }
    };

    int ktn = (K+31)>>5;
    load_tile(0, 0);
    asm volatile("cp.async.commit_group;");
    if (ktn > 1) load_tile(1, 32);
    asm volatile("cp.async.commit_group;");
    for (int kt=0; kt<ktn; kt++) {
        asm volatile("cp.async.wait_group 1;");
        __syncthreads();
        if (kt+2 < ktn) load_tile((kt+2)%3, (kt+2)*32);
        asm volatile("cp.async.commit_group;");
        compute(kt%3);
        __syncthreads();
    }

#pragma unroll
    for (int mt=0;mt<4;mt++) {
        long m = m0 + wm + mt*16 + g;
#pragma unroll
        for (int nt=0;nt<4;nt++) {
            int n = n0 + wn + nt*8 + tig*2;
            if (n < N) {
                float bx = bias[n], by = bias[n+1];
                *(__half2*)&C[m*ldc + n] = __floats2half2_rn(c[mt][nt][0]+bx, c[mt][nt][1]+by);
                *(__half2*)&C[(m+8)*ldc + n] = __floats2half2_rn(c[mt][nt][2]+bx, c[mt][nt][3]+by);
            }
        }
    }
}

// ---------------------------------------------------------------------------
// FP16 NT GEMM. OUT16: 0 = fp32 C, 1 = fp16 C. MODE 1: A shared per 2 z.
// ---------------------------------------------------------------------------
#define HSTR 20
#define HA_WORDS (128*HSTR)
#define HSTG (2*HA_WORDS)

template<int MODE, int OUT16>
__launch_bounds__(256, 2)
__global__ void gemm_h(const __half* __restrict__ A, const __half* __restrict__ B,
                       const float* __restrict__ bias, void* __restrict__ Cv,
                       int M, int N, int K,
                       long sA, long sB, long sBias, long sC, int ldc)
{
    extern __shared__ uint32_t smp[];
    int z = blockIdx.z;
    const __half* Ab = A + (MODE==1 ? (long)(z>>1)*sA : (long)z*sA);
    const __half* Bp = B + (long)z*sB;
    const float* bp = bias + (long)z*sBias;

    int m0 = blockIdx.y*128, n0 = blockIdx.x*128;
    int tid = threadIdx.x;
    int warp = tid>>5, lane = tid&31;
    int g = lane>>2, tig = lane&3;
    int wm = (warp&1)*64, wn = (warp>>1)*32;

    float c[4][4][4];
#pragma unroll
    for (int mt=0;mt<4;mt++)
#pragma unroll
        for (int nt=0;nt<4;nt++)
#pragma unroll
            for (int i=0;i<4;i++) c[mt][nt][i]=0.f;

    int lrow = tid>>1;
    int lseg = (tid&1)*8;
    const __half* arow = Ab + (long)(m0+lrow)*K;
    const __half* brow = Bp + (long)(n0+lrow)*K;
    bool bok = (n0+lrow) < N;

    auto load_tile = [&](int st, int k0) {
        uint32_t* As = smp + st*HSTG;
        uint32_t* Bs = As + HA_WORDS;
        cpa16(s2u(&As[lrow*HSTR + lseg]),     arow + k0 + lseg*2,     16);
        cpa16(s2u(&As[lrow*HSTR + lseg + 4]), arow + k0 + lseg*2 + 8, 16);
        cpa16(s2u(&Bs[lrow*HSTR + lseg]),     bok ? (brow + k0 + lseg*2)     : brow, bok?16:0);
        cpa16(s2u(&Bs[lrow*HSTR + lseg + 4]), bok ? (brow + k0 + lseg*2 + 8) : brow, bok?16:0);
    };
    auto compute = [&](int st) {
        const uint32_t* As = smp + st*HSTG;
        const uint32_t* Bs = As + HA_WORDS;
#pragma unroll
        for (int ks=0;ks<2;ks++) {
            uint32_t a[4][4], b[4][2];
#pragma unroll
            for (int mt=0;mt<4;mt++) {
                int base = (wm + mt*16 + g)*HSTR + ks*8 + tig;
                a[mt][0] = As[base];
                a[mt][1] = As[base + 8*HSTR];
                a[mt][2] = As[base + 4];
                a[mt][3] = As[base + 8*HSTR + 4];
            }
#pragma unroll
            for (int nt=0;nt<4;nt++) {
                int base = (wn + nt*8 + g)*HSTR + ks*8 + tig;
                b[nt][0] = Bs[base];
                b[nt][1] = Bs[base + 4];
            }
#pragma unroll
            for (int mt=0;mt<4;mt++)
#pragma unroll
                for (int nt=0;nt<4;nt++)
                    mma_f16(c[mt][nt], a[mt], b[nt]);
        }
    };

    int ktn = K>>5;
    load_tile(0, 0);
    asm volatile("cp.async.commit_group;");
    if (ktn > 1) load_tile(1, 32);
    asm volatile("cp.async.commit_group;");
    for (int kt=0; kt<ktn; kt++) {
        asm volatile("cp.async.wait_group 1;");
        __syncthreads();
        if (kt+2 < ktn) load_tile((kt+2)%3, (kt+2)*32);
        asm volatile("cp.async.commit_group;");
        compute(kt%3);
        __syncthreads();
    }

#pragma unroll
    for (int mt=0;mt<4;mt++) {
        long m = m0 + wm + mt*16 + g;
#pragma unroll
        for (int nt=0;nt<4;nt++) {
            int n = n0 + wn + nt*8 + tig*2;
            if (n < N) {
                float bx = bp[n], by = bp[n+1];
                float v00 = c[mt][nt][0]+bx, v01 = c[mt][nt][1]+by;
                float v10 = c[mt][nt][2]+bx, v11 = c[mt][nt][3]+by;
                if (OUT16) {
                    __half* Cb = (__half*)Cv + (long)z*sC;
                    *(__half2*)&Cb[m*ldc + n] = __floats2half2_rn(v00, v01);
                    *(__half2*)&Cb[(m+8)*ldc + n] = __floats2half2_rn(v10, v11);
                } else {
                    float* Cb = (float*)Cv + (long)z*sC;
                    float2 v0; v0.x = v00; v0.y = v01;
                    float2 v1; v1.x = v10; v1.y = v11;
                    *(float2*)&Cb[m*ldc + n] = v0;
                    *(float2*)&Cb[(m+8)*ldc + n] = v1;
                }
            }
        }
    }
}

// ---------------------------------------------------------------------------
// Fused fp16 QK^T + softmax -> P_h. Block 128x256, warp 64x64.
// ---------------------------------------------------------------------------
#define QH_B (256*HSTR)
#define QH_STG (HA_WORDS + QH_B)

__launch_bounds__(256, 1)
__global__ void qk_softmax_h(const __half* __restrict__ x, __half* __restrict__ P,
                             float scale)
{
    extern __shared__ uint32_t smp[];
    const int qtab[6]  = {0,0,1,1,2,2};
    const int kvtab[6] = {1,2,0,2,0,1};

    int z = blockIdx.z;
    int p = z>>6, b = z&63;
    const __half* Ab = x + ((long)qtab[p]*BS + (long)b*Ss)*128;
    const __half* Bp = x + ((long)kvtab[p]*BS + (long)b*Ss)*128;
    __half* Cb = P + (long)z*Ss*Ss;
    int m0 = blockIdx.y*128;
    int tid = threadIdx.x;
    int warp = tid>>5, lane = tid&31;
    int g = lane>>2, tig = lane&3;
    int wm = (warp&1)*64, wn = (warp>>1)*64;

    float c[4][8][4];
#pragma unroll
    for (int mt=0;mt<4;mt++)
#pragma unroll
        for (int nt=0;nt<8;nt++)
#pragma unroll
            for (int i=0;i<4;i++) c[mt][nt][i]=0.f;

    int lrow = tid>>1;
    int lseg = (tid&1)*8;
    const __half* arow = Ab + (long)(m0+lrow)*128;
    const __half* brow = Bp + (long)tid*128;

    auto load_tile = [&](int st, int k0) {
        uint32_t* As = smp + st*QH_STG;
        uint32_t* Bs = As + HA_WORDS;
        cpa16(s2u(&As[lrow*HSTR + lseg]),     arow + k0 + lseg*2,     16);
        cpa16(s2u(&As[lrow*HSTR + lseg + 4]), arow + k0 + lseg*2 + 8, 16);
#pragma unroll
        for (int h=0;h<4;h++)
            cpa16(s2u(&Bs[tid*HSTR + h*4]), brow + k0 + h*8, 16);
    };
    auto compute = [&](int st) {
        const uint32_t* As = smp + st*QH_STG;
        const uint32_t* Bs = As + HA_WORDS;
#pragma unroll
        for (int ks=0;ks<2;ks++) {
            uint32_t a[4][4], bb[8][2];
#pragma unroll
            for (int mt=0;mt<4;mt++) {
                int base = (wm + mt*16 + g)*HSTR + ks*8 + tig;
                a[mt][0] = As[base];
                a[mt][1] = As[base + 8*HSTR];
                a[mt][2] = As[base + 4];
                a[mt][3] = As[base + 8*HSTR + 4];
            }
#pragma unroll
            for (int nt=0;nt<8;nt++) {
                int base = (wn + nt*8 + g)*HSTR + ks*8 + tig;
                bb[nt][0] = Bs[base];
                bb[nt][1] = Bs[base + 4];
            }
#pragma unroll
            for (int mt=0;mt<4;mt++)
#pragma unroll
                for (int nt=0;nt<8;nt++)
                    mma_f16(c[mt][nt], a[mt], bb[nt]);
        }
    };

    load_tile(0, 0);
    asm volatile("cp.async.commit_group;");
    load_tile(1, 32);
    asm volatile("cp.async.commit_group;");
    for (int kt=0; kt<4; kt++) {
        asm volatile("cp.async.wait_group 1;");
        __syncthreads();
        if (kt+2 < 4) load_tile((kt+2)%3, (kt+2)*32);
        asm volatile("cp.async.commit_group;");
        compute(kt%3);
        __syncthreads();
    }

#pragma unroll
    for (int mt=0;mt<4;mt++)
#pragma unroll
        for (int nt=0;nt<8;nt++)
#pragma unroll
            for (int i=0;i<4;i++) c[mt][nt][i] *= scale;

    float* red = (float*)smp;
    int wcol = warp>>1;
    float rmax[4][2], rinv[4][2];

#pragma unroll
    for (int mt=0;mt<4;mt++)
#pragma unroll
        for (int h=0;h<2;h++) {
            float m = -1e30f;
#pragma unroll
            for (int nt=0;nt<8;nt++)
                m = fmaxf(m, fmaxf(c[mt][nt][2*h], c[mt][nt][2*h+1]));
            m = fmaxf(m, __shfl_xor_sync(0xffffffffu, m, 1));
            m = fmaxf(m, __shfl_xor_sync(0xffffffffu, m, 2));
            if (tig == 0) red[(wm + mt*16 + g + h*8)*4 + wcol] = m;
        }
    __syncthreads();
#pragma unroll
    for (int mt=0;mt<4;mt++)
#pragma unroll
        for (int h=0;h<2;h++) {
            int r = wm + mt*16 + g + h*8;
            rmax[mt][h] = fmaxf(fmaxf(red[r*4], red[r*4+1]),
                                fmaxf(red[r*4+2], red[r*4+3]));
        }
    __syncthreads();
#pragma unroll
    for (int mt=0;mt<4;mt++)
#pragma unroll
        for (int h=0;h<2;h++) {
            float s = 0.f;
#pragma unroll
            for (int nt=0;nt<8;nt++) {
                float e0 = __expf(c[mt][nt][2*h]   - rmax[mt][h]);
                float e1 = __expf(c[mt][nt][2*h+1] - rmax[mt][h]);
                c[mt][nt][2*h]   = e0;
                c[mt][nt][2*h+1] = e1;
                s += e0 + e1;
            }
            s += __shfl_xor_sync(0xffffffffu, s, 1);
            s += __shfl_xor_sync(0xffffffffu, s, 2);
            if (tig == 0) red[(wm + mt*16 + g + h*8)*4 + wcol] = s;
        }
    __syncthreads();
#pragma unroll
    for (int mt=0;mt<4;mt++)
#pragma unroll
        for (int h=0;h<2;h++) {
            int r = wm + mt*16 + g + h*8;
            rinv[mt][h] = 1.f/(red[r*4] + red[r*4+1] + red[r*4+2] + red[r*4+3]);
        }
#pragma unroll
    for (int mt=0;mt<4;mt++)
#pragma unroll
        for (int h=0;h<2;h++) {
            long row = m0 + wm + mt*16 + g + h*8;
#pragma unroll
            for (int nt=0;nt<8;nt++) {
                int col = wn + nt*8 + tig*2;
                *(__half2*)&Cb[row*256 + col] =
                    __floats2half2_rn(c[mt][nt][2*h]   * rinv[mt][h],
                                      c[mt][nt][2*h+1] * rinv[mt][h]);
            }
        }
}

// ---------------------------------------------------------------------------
// Merged PV (fp16), continuous 16-ktile pipeline over both KV segments.
// ---------------------------------------------------------------------------
__launch_bounds__(256, 2)
__global__ void pv_h(const __half* __restrict__ P, const __half* __restrict__ xT,
                     float* __restrict__ tstep, __half* __restrict__ tstep_h)
{
    extern __shared__ uint32_t smp[];
    const int kvtab[6] = {1,2,0,2,0,1};
    int z = blockIdx.z;
    int qq = z>>6, b = z&63;
    float* Cb = tstep + (long)qq*128 + (long)b*Ss*384;
    __half* Ch = tstep_h + (long)qq*128 + (long)b*Ss*384;

    int m0 = blockIdx.y*128;
    int tid = threadIdx.x;
    int warp = tid>>5, lane = tid&31;
    int g = lane>>2, tig = lane&3;
    int wm = (warp&1)*64, wn = (warp>>1)*32;

    float c[4][4][4];
#pragma unroll
    for (int mt=0;mt<4;mt++)
#pragma unroll
        for (int nt=0;nt<4;nt++)
#pragma unroll
            for (int i=0;i<4;i++) c[mt][nt][i]=0.f;

    int lrow = tid>>1;
    int lseg = (tid&1)*8;

    auto load_tile = [&](int st, int gk) {
        int p = 2*qq + (gk>>3);
        int k0 = (gk&7)*32;
        const __half* ar = P + ((long)p*64 + b)*(long)Ss*Ss + (long)(m0+lrow)*Ss + k0;
        const __half* br = xT + ((long)kvtab[p]*64 + b)*128l*Ss + (long)lrow*Ss + k0;
        uint32_t* As = smp + st*HSTG;
        uint32_t* Bs = As + HA_WORDS;
        cpa16(s2u(&As[lrow*HSTR + lseg]),     ar + lseg*2,     16);
        cpa16(s2u(&As[lrow*HSTR + lseg + 4]), ar + lseg*2 + 8, 16);
        cpa16(s2u(&Bs[lrow*HSTR + lseg]),     br + lseg*2,     16);
        cpa16(s2u(&Bs[lrow*HSTR + lseg + 4]), br + lseg*2 + 8, 16);
    };
    auto compute = [&](int st) {
        const uint32_t* As = smp + st*HSTG;
        const uint32_t* Bs = As + HA_WORDS;
#pragma unroll
        for (int ks=0;ks<2;ks++) {
            uint32_t a[4][4], bb[4][2];
#pragma unroll
            for (int mt=0;mt<4;mt++) {
                int base = (wm + mt*16 + g)*HSTR + ks*8 + tig;
                a[mt][0] = As[base];
                a[mt][1] = As[base + 8*HSTR];
                a[mt][2] = As[base + 4];
                a[mt][3] = As[base + 8*HSTR + 4];
            }
#pragma unroll
            for (int nt=0;nt<4;nt++) {
                int base = (wn + nt*8 + g)*HSTR + ks*8 + tig;
                bb[nt][0] = Bs[base];
                bb[nt][1] = Bs[base + 4];
            }
#pragma unroll
            for (int mt=0;mt<4;mt++)
#pragma unroll
                for (int nt=0;nt<4;nt++)
                    mma_f16(c[mt][nt], a[mt], bb[nt]);
        }
    };

    load_tile(0, 0);
    asm volatile("cp.async.commit_group;");
    load_tile(1, 1);
    asm volatile("cp.async.commit_group;");
    for (int gk=0; gk<16; gk++) {
        asm volatile("cp.async.wait_group 1;");
        __syncthreads();
        if (gk+2 < 16) load_tile((gk+2)%3, gk+2);
        asm volatile("cp.async.commit_group;");
        compute(gk%3);
        __syncthreads();
    }

#pragma unroll
    for (int mt=0;mt<4;mt++) {
        long m = m0 + wm + mt*16 + g;
#pragma unroll
        for (int nt=0;nt<4;nt++) {
            int n = wn + nt*8 + tig*2;
            float2 o0 = *(const float2*)&Cb[m*384 + n];
            float2 o1 = *(const float2*)&Cb[(m+8)*384 + n];
            float2 v0, v1;
            v0.x = c[mt][nt][0]+o0.x; v0.y = c[mt][nt][1]+o0.y;
            v1.x = c[mt][nt][2]+o1.x; v1.y = c[mt][nt][3]+o1.y;
            *(float2*)&Cb[m*384 + n] = v0;
            *(float2*)&Cb[(m+8)*384 + n] = v1;
            *(__half2*)&Ch[m*384 + n] = __floats2half2_rn(v0.x, v0.y);
            *(__half2*)&Ch[(m+8)*384 + n] = __floats2half2_rn(v1.x, v1.y);
        }
    }
}

// ---------------------------------------------------------------------------
// biGRU with next-step xg register prefetch.
// ---------------------------------------------------------------------------
__launch_bounds__(192, 3)
__global__ void gru_rec(const float* __restrict__ xg_all, const float* __restrict__ Wh,
                        const float* __restrict__ bh, __half* __restrict__ x_h,
                        float* __restrict__ tstep)
{
    int bx = blockIdx.x;
    int m = bx>>7, d = (bx>>6)&1, b = bx&63, md = m*2+d;
    int j = threadIdx.x;
    ull w2[32];
#pragma unroll
    for (int q=0;q<32;q++)
        w2[q] = pk(Wh[((long)md*64 + 2*q)*192 + j], Wh[((long)md*64 + 2*q+1)*192 + j]);
    float bhj = bh[md*192 + j];
    __shared__ alignas(16) float h_s[64];
    __shared__ float pre_s[192], xn_s[64];
    uint32_t hsa = s2u(h_s);
    if (j<64) h_s[j]=0.f;
    const float* xg = xg_all + ((long)md*BS + (long)b*Ss)*192;
    int s0 = d ? (Ss-1) : 0;
    float xg_cur = xg[(long)s0*192 + j];
    for (int t=0;t<Ss;t++) {
        int s = d ? (Ss-1-t) : t;
        int sn = d ? (Ss-2-t) : (t+1);
        sn = sn < 0 ? 0 : (sn > Ss-1 ? Ss-1 : sn);
        __syncthreads();
        float xg_nxt = xg[(long)sn*192 + j];
        ull a0 = pk(bhj, 0.f), a1 = pk(0.f, 0.f);
#pragma unroll
        for (int q=0;q<16;q++) {
            ull h0,h1; lds2x64(h0,h1, hsa + q*16);
            ffma2(a0, h0, w2[2*q]);
            ffma2(a1, h1, w2[2*q+1]);
        }
        float2 f0 = upk(a0), f1 = upk(a1);
        float acc = f0.x + f0.y + f1.x + f1.y;
        float xgv = xg_cur;
        if (j<128) pre_s[j] = acc + xgv;
        else { pre_s[j] = acc; xn_s[j-128] = xgv; }
        __syncthreads();
        if (j<64) {
            float r = sigf(pre_s[j]);
            float zg = sigf(pre_s[64+j]);
            float n = tanhfast(xn_s[j] + r*pre_s[128+j]);
            float hn = (1.f-zg)*n + zg*h_s[j];
            h_s[j] = hn;
            long row = (long)b*Ss + s;
            x_h[((long)m*BS + row)*128 + d*64 + j] = __float2half(hn);
            tstep[row*384 + m*128 + d*64 + j] = hn;
        }
        xg_cur = xg_nxt;
    }
}

// ---------------------------------------------------------------------------
// biLSTM with next-step xg register prefetch.
// ---------------------------------------------------------------------------
__launch_bounds__(512, 1)
__global__ void lstm_rec(const float* __restrict__ xg_all, const float* __restrict__ Wh,
                         const float* __restrict__ bh, __half* __restrict__ sf_h)
{
    extern __shared__ unsigned char smraw[];
    ull*   Wlo2  = (ull*)smraw;
    float* h_s   = (float*)(smraw + 16*512*8);
    float* pre_s = (float*)(smraw + 16*512*8 + 512);
    int bx = blockIdx.x, d = bx>>6, b = bx&63;
    int j = threadIdx.x;
    const float* Whd = Wh + (long)d*128*512;
    ull w2[48];
#pragma unroll
    for (int q=0;q<48;q++)
        w2[q] = pk(Whd[(long)(2*q)*512 + j], Whd[(long)(2*q+1)*512 + j]);
    for (int q=0;q<16;q++)
        Wlo2[q*512 + j] = pk(Whd[(long)(96+2*q)*512 + j], Whd[(long)(97+2*q)*512 + j]);
    float bhj = bh[d*512 + j];
    float c = 0.f;
    if (j<128) h_s[j]=0.f;
    uint32_t hsa = s2u(h_s);
    const float* xg = xg_all + ((long)d*BS + (long)b*Ss)*512;
    int s0 = d ? (Ss-1) : 0;
    float xg_cur = xg[(long)s0*512 + j];
    for (int t=0;t<Ss;t++) {
        int s = d ? (Ss-1-t) : t;
        int sn = d ? (Ss-2-t) : (t+1);
        sn = sn < 0 ? 0 : (sn > Ss-1 ? Ss-1 : sn);
        __syncthreads();
        float xg_nxt = xg[(long)sn*512 + j];
        ull a0 = pk(bhj, 0.f), a1 = pk(0.f, 0.f);
#pragma unroll
        for (int q=0;q<24;q++) {
            ull h0,h1; lds2x64(h0,h1, hsa + q*16);
            ffma2(a0, h0, w2[2*q]);
            ffma2(a1, h1, w2[2*q+1]);
        }
#pragma unroll
        for (int q=0;q<8;q++) {
            ull h0,h1; lds2x64(h0,h1, hsa + 384 + q*16);
            ffma2(a0, h0, Wlo2[(2*q)*512 + j]);
            ffma2(a1, h1, Wlo2[(2*q+1)*512 + j]);
        }
        float2 f0 = upk(a0), f1 = upk(a1);
        float acc = f0.x + f0.y + f1.x + f1.y + xg_cur;
        pre_s[j] = acc;
        __syncthreads();
        if (j<128) {
            float ig = pre_s[j], fg = pre_s[128+j], gg = pre_s[256+j], og = pre_s[384+j];
            c = sigf(fg)*c + sigf(ig)*tanhfast(gg);
            float h = sigf(og)*tanhfast(c);
            h_s[j] = h;
            sf_h[((long)b*Ss + s)*256 + d*128 + j] = __float2half(h);
        }
        xg_cur = xg_nxt;
    }
}

// ---------------------------------------------------------------------------
// RGN with next-step xg register prefetch.
// ---------------------------------------------------------------------------
__launch_bounds__(384, 1)
__global__ void rgn_rec(const float* __restrict__ xg_all, const float* __restrict__ Wh,
                        const float* __restrict__ state0, const float* __restrict__ state1,
                        float* __restrict__ outbuf)
{
    __shared__ alignas(16) float h_s[128];
    __shared__ float pre_s[384], xn_s[128];
    int bx = blockIdx.x, kk = bx>>6, b = bx&63;
    int j = threadIdx.x;
    const float* Whd = Wh + (long)kk*128*384;
    ull w2[64];
#pragma unroll
    for (int q=0;q<64;q++)
        w2[q] = pk(Whd[(long)(2*q)*384 + j], Whd[(long)(2*q+1)*384 + j]);
    if (j<128) h_s[j] = (kk==0?state0:state1)[b*128 + j];
    uint32_t hsa = s2u(h_s);
    const float* xg = xg_all + ((long)kk*BS + (long)b*Ss)*384;
    int s0 = kk ? (Ss-1) : 0;
    float xg_cur = xg[(long)s0*384 + j];
    for (int t=0;t<Ss;t++) {
        int sn = kk ? (Ss-2-t) : (t+1);
        sn = sn < 0 ? 0 : (sn > Ss-1 ? Ss-1 : sn);
        __syncthreads();
        float xg_nxt = xg[(long)sn*384 + j];
        ull a0 = pk(0.f, 0.f), a1 = pk(0.f, 0.f);
#pragma unroll
        for (int q=0;q<32;q++) {
            ull h0,h1; lds2x64(h0,h1, hsa + q*16);
            ffma2(a0, h0, w2[2*q]);
            ffma2(a1, h1, w2[2*q+1]);
        }
        float2 f0 = upk(a0), f1 = upk(a1);
        float acc = f0.x + f0.y + f1.x + f1.y;
        float xgv = xg_cur;
        if (j<256) pre_s[j] = acc + xgv;
        else { pre_s[j] = acc; xn_s[j-256] = xgv; }
        __syncthreads();
        if (j<128) {
            float r = sigf(pre_s[j]);
            float z = sigf(pre_s[128+j]);
            float n = tanhfast(xn_s[j] + r*pre_s[256+j]);
            h_s[j] = (1.f-z)*n + z*h_s[j];
        }
        xg_cur = xg_nxt;
    }
    __syncthreads();
    if (j<128) outbuf[((long)kk*64 + b)*128 + j] = h_s[j];
}

__launch_bounds__(32)
__global__ void final_fc(const float* __restrict__ outbuf,
                         const float* __restrict__ fc1W, const float* __restrict__ fc1b,
                         const float* __restrict__ fc2W, const float* __restrict__ fc2b,
                         float* __restrict__ out)
{
    int b = blockIdx.x, t = threadIdx.x;
    float acc = fc1b[t];
    for (int k=0;k<128;k++) {
        float x = outbuf[b*128+k] + outbuf[64*128 + b*128 + k];
        acc += x * fc1W[k*32 + t];
    }
    float h = acc > 0.f ? acc : 0.01f*acc;
    float v = h * fc2W[t];
#pragma unroll
    for (int o=16;o;o>>=1) v += __shfl_xor_sync(0xffffffffu, v, o);
    if (t==0) out[b] = v + fc2b[0];
}

extern "C" void kernel_launch(void* const* d_in, const int* in_sizes, int n_in,
                              void* d_out, int out_size)
{
    (void)in_sizes; (void)n_in; (void)out_size;
    const int*   sentences = (const int*)  d_in[0];
    const float* acoustic  = (const float*)d_in[1];
    const float* video     = (const float*)d_in[2];
    const float* state0    = (const float*)d_in[3];
    const float* state1    = (const float*)d_in[4];
    const float* emb       = (const float*)d_in[5];
    const float* proj_l_W  = (const float*)d_in[6];
    const float* proj_l_b  = (const float*)d_in[7];
    const float* proj_a_W  = (const float*)d_in[8];
    const float* proj_a_b  = (const float*)d_in[9];
    const float* proj_v_W  = (const float*)d_in[10];
    const float* proj_v_b  = (const float*)d_in[11];
    const float* gru_Wi    = (const float*)d_in[12];
    const float* gru_Wh    = (const float*)d_in[13];
    const float* gru_bi    = (const float*)d_in[14];
    const float* gru_bh    = (const float*)d_in[15];
    const float* lstm_Wi   = (const float*)d_in[16];
    const float* lstm_Wh   = (const float*)d_in[17];
    const float* lstm_bi   = (const float*)d_in[18];
    const float* lstm_bh   = (const float*)d_in[19];
    const float* rgn_Wx    = (const float*)d_in[20];
    const float* rgn_Wh    = (const float*)d_in[21];
    const float* rgn_b     = (const float*)d_in[22];
    const float* fc1_W     = (const float*)d_in[23];
    const float* fc1_b     = (const float*)d_in[24];
    const float* fc2_W     = (const float*)d_in[25];
    const float* fc2_b     = (const float*)d_in[26];
    float* out = (float*)d_out;

    float *xg_gru,*tstep,*xg_lstm,*xg_rgn,*rgn_out;
    __half *seq_h,*x_h,*xT_h,*P_h,*tstep_h,*sf_h,*WT_h,*ac_h,*vid_h;
    cudaGetSymbolAddress((void**)&xg_gru, g_xg_gru);
    cudaGetSymbolAddress((void**)&tstep, g_tstep);
    cudaGetSymbolAddress((void**)&xg_lstm, g_xg_lstm);
    cudaGetSymbolAddress((void**)&xg_rgn, g_xg_rgn);
    cudaGetSymbolAddress((void**)&rgn_out, g_rgn_out);
    cudaGetSymbolAddress((void**)&seq_h, g_seq_h);
    cudaGetSymbolAddress((void**)&x_h, g_x_h);
    cudaGetSymbolAddress((void**)&xT_h, g_xT_h);
    cudaGetSymbolAddress((void**)&P_h, g_P_h);
    cudaGetSymbolAddress((void**)&tstep_h, g_tstep_h);
    cudaGetSymbolAddress((void**)&sf_h, g_sf_h);
    cudaGetSymbolAddress((void**)&WT_h, g_WT_h);
    cudaGetSymbolAddress((void**)&ac_h, g_ac_h);
    cudaGetSymbolAddress((void**)&vid_h, g_vid_h);
    __half* gruT  = WT_h;
    __half* lstmT = gruT + 6*192*128;
    __half* rgnT  = lstmT + 2l*512*384;
    __half* projaT = rgnT + 2l*384*256;
    __half* projvT = projaT + 128*96;

    const size_t shm_tf3 = 3u*STG_WORDS*4u;
    const size_t shm_h   = 3u*HSTG*4u;
    const size_t shm_qk  = 3u*QH_STG*4u;
    cudaFuncSetAttribute(gemm_tf, cudaFuncAttributeMaxDynamicSharedMemorySize, (int)shm_tf3);
    cudaFuncSetAttribute(gemm_h<0,0>, cudaFuncAttributeMaxDynamicSharedMemorySize, (int)shm_h);
    cudaFuncSetAttribute(gemm_h<1,0>, cudaFuncAttributeMaxDynamicSharedMemorySize, (int)shm_h);
    cudaFuncSetAttribute(gemm_h<0,1>, cudaFuncAttributeMaxDynamicSharedMemorySize, (int)shm_h);
    cudaFuncSetAttribute(qk_softmax_h, cudaFuncAttributeMaxDynamicSharedMemorySize, (int)shm_qk);
    cudaFuncSetAttribute(pv_h, cudaFuncAttributeMaxDynamicSharedMemorySize, (int)shm_h);
    cudaFuncSetAttribute(lstm_rec, cudaFuncAttributeMaxDynamicSharedMemorySize, 72*1024);

    // weight transposes (fp32 [K,N] -> fp16 [N,KP])
    wtrans<<<dim3(4, 6, 6), dim3(32,8)>>>(gru_Wi, gruT, 128, 192, 128);
    wtrans<<<dim3(12, 16, 2), dim3(32,8)>>>(lstm_Wi, lstmT, 384, 512, 384);
    wtrans<<<dim3(8, 12, 2), dim3(32,8)>>>(rgn_Wx, rgnT, 256, 384, 256);
    wtrans<<<dim3(3, 4, 1), dim3(32,8)>>>(proj_a_W, projaT, 74, 128, 96);
    wtrans<<<dim3(2, 4, 1), dim3(32,8)>>>(proj_v_W, projvT, 35, 128, 64);

    // input conversions (pad K)
    conv_pad<<<1024, 256>>>(acoustic, ac_h, BS, 74, 96);
    conv_pad<<<1024, 256>>>(video, vid_h, BS, 35, 64);

    // modality projections -> seq_h
    gemm_tf<<<dim3(1, BS/128, 1), 256, shm_tf3>>>(
        emb, proj_l_W, proj_l_b, seq_h, BS, 128, DL, 128, sentences);
    gemm_h<0,1><<<dim3(1, BS/128, 1), 256, shm_h>>>(
        ac_h, projaT, proj_a_b, seq_h + 1l*BS*DH, BS, 128, 96, 0, 0, 0, 0, 128);
    gemm_h<0,1><<<dim3(1, BS/128, 1), 256, shm_h>>>(
        vid_h, projvT, proj_v_b, seq_h + 2l*BS*DH, BS, 128, 64, 0, 0, 0, 0, 128);

    // GRU input projections (z=6)
    gemm_h<1,0><<<dim3(2, BS/128, 6), 256, shm_h>>>(
        seq_h, gruT, gru_bi, xg_gru, BS, 192, 128,
        (long)BS*DH, 192l*128, 192, (long)BS*192, 192);

    gru_rec<<<3*2*64, 192>>>(xg_gru, gru_Wh, gru_bh, x_h, tstep);
    xtrans<<<dim3(192, 4), 256>>>(x_h, xT_h);

    // JCAF
    const float scale = 0.08838834764831845f;
    qk_softmax_h<<<dim3(1, 2, 384), 256, shm_qk>>>(x_h, P_h, scale);
    pv_h<<<dim3(1, 2, 192), 256, shm_h>>>(P_h, xT_h, tstep, tstep_h);

    // LSTM input projections (z=2)
    gemm_h<0,0><<<dim3(4, BS/128, 2), 256, shm_h>>>(
        tstep_h, lstmT, lstm_bi, xg_lstm, BS, 512, 384,
        0, 512l*384, 512, (long)BS*512, 512);

    lstm_rec<<<2*64, 512, 16*512*8 + 512 + 2048>>>(xg_lstm, lstm_Wh, lstm_bh, sf_h);

    // RGN input projections (z=2)
    gemm_h<0,0><<<dim3(3, BS/128, 2), 256, shm_h>>>(
        sf_h, rgnT, rgn_b, xg_rgn, BS, 384, 256,
        0, 384l*256, 384, (long)BS*384, 384);

    rgn_rec<<<2*64, 384>>>(xg_rgn, rgn_Wh, state0, state1, rgn_out);

    final_fc<<<Bb, 32>>>(rgn_out, fc1_W, fc1_b, fc2_W, fc2_b, out);
}

// round 10
// speedup vs baseline: 1.1890x; 1.0220x over previous
#include <cuda_runtime.h>
#include <cuda_fp16.h>
#include <math.h>
#include <stdint.h>

#define Bb 64
#define Ss 256
#define BS (Bb*Ss)
#define DL 300
#define DA 74
#define DV 35
#define DH 128

// fp32 scratch
__device__ float g_xg_gru[6u*BS*192];
__device__ float g_tstep[(unsigned)BS*384];
__device__ float g_xg_lstm[2u*BS*512];
__device__ float g_xg_rgn[2u*BS*384];
__device__ float g_rgn_out[2u*Bb*128];
// fp16 scratch
__device__ __half g_seq_h[3u*BS*DH];
__device__ __half g_x_h[3u*BS*DH];
__device__ __half g_xT_h[3u*(unsigned)Bb*128*Ss];
__device__ __half g_P_h[6u*(unsigned)Bb*Ss*Ss];
__device__ __half g_tstep_h[(unsigned)BS*384];
__device__ __half g_sf_h[(unsigned)BS*256];
__device__ __half g_ac_h[(unsigned)BS*96];
__device__ __half g_vid_h[(unsigned)BS*64];
__device__ __half g_WT_h[757760];

typedef unsigned long long ull;

__device__ __forceinline__ uint32_t s2u(const void* p) {
    return (uint32_t)__cvta_generic_to_shared(p);
}
__device__ __forceinline__ void cpa16(uint32_t dst, const void* src, int bytes) {
    asm volatile("cp.async.cg.shared.global [%0], [%1], 16, %2;"
                 :: "r"(dst), "l"(src), "r"(bytes));
}
__device__ __forceinline__ void mma_tf32(float c[4], const uint32_t a[4], const uint32_t b[2]) {
    asm volatile(
        "mma.sync.aligned.m16n8k8.row.col.f32.tf32.tf32.f32 "
        "{%0,%1,%2,%3}, {%4,%5,%6,%7}, {%8,%9}, {%0,%1,%2,%3};"
        : "+f"(c[0]), "+f"(c[1]), "+f"(c[2]), "+f"(c[3])
        : "r"(a[0]), "r"(a[1]), "r"(a[2]), "r"(a[3]), "r"(b[0]), "r"(b[1]));
}
__device__ __forceinline__ void mma_f16(float c[4], const uint32_t a[4], const uint32_t b[2]) {
    asm volatile(
        "mma.sync.aligned.m16n8k16.row.col.f32.f16.f16.f32 "
        "{%0,%1,%2,%3}, {%4,%5,%6,%7}, {%8,%9}, {%0,%1,%2,%3};"
        : "+f"(c[0]), "+f"(c[1]), "+f"(c[2]), "+f"(c[3])
        : "r"(a[0]), "r"(a[1]), "r"(a[2]), "r"(a[3]), "r"(b[0]), "r"(b[1]));
}
__device__ __forceinline__ ull pk(float x, float y) {
    ull r; asm("mov.b64 %0,{%1,%2};" : "=l"(r) : "f"(x), "f"(y)); return r;
}
__device__ __forceinline__ float2 upk(ull v) {
    float2 f; asm("mov.b64 {%0,%1},%2;" : "=f"(f.x), "=f"(f.y) : "l"(v)); return f;
}
__device__ __forceinline__ void ffma2(ull &d, ull a, ull b) {
    asm volatile("fma.rn.f32x2 %0, %1, %2, %0;" : "+l"(d) : "l"(a), "l"(b));
}
__device__ __forceinline__ void lds2x64(ull &a, ull &b, uint32_t addr) {
    asm volatile("ld.shared.v2.b64 {%0,%1},[%2];" : "=l"(a), "=l"(b) : "r"(addr));
}
__device__ __forceinline__ float sigf(float x) { return 1.f/(1.f + __expf(-x)); }
__device__ __forceinline__ float tanhfast(float x) {
    float y; asm("tanh.approx.f32 %0,%1;" : "=f"(y) : "f"(x)); return y;
}

// ---------------------------------------------------------------------------
// ALL weight transposes in one launch. 740 tiles:
//   [0,144)   gru  : K=128 N=192 KP=128 z=6  (4x * 6y per z)
//   [144,528) lstm : K=384 N=512 KP=384 z=2  (12x * 16y per z)
//   [528,720) rgn  : K=256 N=384 KP=256 z=2  (8x * 12y per z)
//   [720,732) proja: K=74  N=128 KP=96       (3x * 4y)
//   [732,740) projv: K=35  N=128 KP=64       (2x * 4y)
// ---------------------------------------------------------------------------
__global__ void wtrans_all(const float* __restrict__ gru_Wi,
                           const float* __restrict__ lstm_Wi,
                           const float* __restrict__ rgn_Wx,
                           const float* __restrict__ pa,
                           const float* __restrict__ pv,
                           __half* __restrict__ WT)
{
    __half* gruT  = WT;
    __half* lstmT = gruT + 6*192*128;
    __half* rgnT  = lstmT + 2l*512*384;
    __half* projaT = rgnT + 2l*384*256;
    __half* projvT = projaT + 128*96;

    int bid = blockIdx.x;
    const float* in; __half* out;
    int K, N, KP, k0, n0;
    if (bid < 144) {
        int z = bid/24, rem = bid%24;
        K = 128; N = 192; KP = 128;
        k0 = (rem%4)*32; n0 = (rem/4)*32;
        in = gru_Wi + (long)z*K*N; out = gruT + (long)z*N*KP;
    } else if (bid < 528) {
        int b2 = bid-144; int z = b2/192, rem = b2%192;
        K = 384; N = 512; KP = 384;
        k0 = (rem%12)*32; n0 = (rem/12)*32;
        in = lstm_Wi + (long)z*K*N; out = lstmT + (long)z*N*KP;
    } else if (bid < 720) {
        int b2 = bid-528; int z = b2/96, rem = b2%96;
        K = 256; N = 384; KP = 256;
        k0 = (rem%8)*32; n0 = (rem/8)*32;
        in = rgn_Wx + (long)z*K*N; out = rgnT + (long)z*N*KP;
    } else if (bid < 732) {
        int rem = bid-720;
        K = 74; N = 128; KP = 96;
        k0 = (rem%3)*32; n0 = (rem/3)*32;
        in = pa; out = projaT;
    } else {
        int rem = bid-732;
        K = 35; N = 128; KP = 64;
        k0 = (rem%2)*32; n0 = (rem/2)*32;
        in = pv; out = projvT;
    }

    __shared__ float t[32][33];
    int tx = threadIdx.x, ty = threadIdx.y;
#pragma unroll
    for (int i=0;i<32;i+=8) {
        int k = k0+ty+i, n = n0+tx;
        t[ty+i][tx] = (k<K && n<N) ? in[(long)k*N+n] : 0.f;
    }
    __syncthreads();
#pragma unroll
    for (int i=0;i<32;i+=8) {
        int n = n0+ty+i, k = k0+tx;
        if (n<N && k<KP) out[(long)n*KP+k] = __float2half(t[tx][ty+i]);
    }
}

// both input conversions in one launch
__global__ void conv2(const float* __restrict__ ac, __half* __restrict__ ach,
                      const float* __restrict__ vid, __half* __restrict__ vidh)
{
    const long TOT_A = (long)BS*96;
    const long TOT_V = (long)BS*64;
    for (long i = (long)blockIdx.x*blockDim.x + threadIdx.x; i < TOT_A + TOT_V;
         i += (long)gridDim.x*blockDim.x) {
        if (i < TOT_A) {
            long row = i/96; int k = (int)(i - row*96);
            ach[i] = (k<74) ? __float2half(ac[row*74 + k]) : __float2half(0.f);
        } else {
            long j = i - TOT_A;
            long row = j/64; int k = (int)(j - row*64);
            vidh[j] = (k<35) ? __float2half(vid[row*35 + k]) : __float2half(0.f);
        }
    }
}

// ---------------------------------------------------------------------------
// x_h -> xT_h transpose
// ---------------------------------------------------------------------------
__global__ void xtrans(const __half* __restrict__ xin, __half* __restrict__ xout)
{
    __shared__ __half sm[64][130];
    int mb = blockIdx.x;
    int m = mb>>6, b = mb&63;
    int s0 = blockIdx.y*64;
    int tid = threadIdx.x;
    const __half* src = xin + ((long)m*BS + (long)b*Ss + s0)*128;
#pragma unroll
    for (int i=0;i<32;i++) {
        int idx = tid + i*256;
        int s = idx>>7, d = idx&127;
        sm[s][d] = src[(long)s*128 + d];
    }
    __syncthreads();
    __half* dst = xout + (long)mb*128*Ss;
#pragma unroll
    for (int i=0;i<32;i++) {
        int idx = tid + i*256;
        int d = idx>>6, ss = idx&63;
        dst[(long)d*Ss + s0 + ss] = sm[ss][d];
    }
}

// ---------------------------------------------------------------------------
// TF32 GEMM (embedding projection only). fp16 output, 3-stage pipeline.
// ---------------------------------------------------------------------------
#define ASTR 36
#define BSTR 136
#define AWORDS (128*ASTR)
#define STG_WORDS (2*AWORDS)

__launch_bounds__(256, 2)
__global__ void gemm_tf(const float* __restrict__ A, const float* __restrict__ W,
                        const float* __restrict__ bias, __half* __restrict__ C,
                        int M, int N, int K, int ldc,
                        const int* __restrict__ gidx)
{
    extern __shared__ uint32_t smp[];
    int m0 = blockIdx.y*128, n0 = blockIdx.x*128;
    int tid = threadIdx.x;
    int warp = tid>>5, lane = tid&31;
    int g = lane>>2, tig = lane&3;
    int wm = (warp&1)*64, wn = (warp>>1)*32;

    float c[4][4][4];
#pragma unroll
    for (int mt=0;mt<4;mt++)
#pragma unroll
        for (int nt=0;nt<4;nt++)
#pragma unroll
            for (int i=0;i<4;i++) c[mt][nt][i]=0.f;

    int lrow = tid>>3;
    int akq  = (tid&7)*4;
    const float* arp[4];
#pragma unroll
    for (int p=0;p<4;p++)
        arp[p] = A + (long)gidx[m0 + lrow + p*32]*(long)K;
    int bnk = tid>>5;
    int bn4 = (tid&31)*4;

    auto load_tile = [&](int st, int k0) {
        uint32_t* As = smp + st*STG_WORDS;
        uint32_t* Bs = As + AWORDS;
#pragma unroll
        for (int p=0;p<4;p++) {
            int gk = k0 + akq;
            int bytes = (K - gk)*4; bytes = bytes<0?0:(bytes>16?16:bytes);
            const float* src = bytes ? (arp[p] + gk) : A;
            cpa16(s2u(&As[(lrow + p*32)*ASTR + akq]), src, bytes);
        }
#pragma unroll
        for (int p=0;p<4;p++) {
            int k = bnk + p*8;
            int ok = ((k0+k) < K) && ((n0+bn4) < N);
            const float* src = ok ? (W + (long)(k0+k)*N + n0 + bn4) : W;
            cpa16(s2u(&Bs[k*BSTR + bn4]), src, ok ? 16 : 0);
        }
    };
    auto compute = [&](int st) {
        const uint32_t* As = smp + st*STG_WORDS;
        const uint32_t* Bs = As + AWORDS;
#pragma unroll
        for (int ks=0;ks<4;ks++) {
            uint32_t a[4][4], b[4][2];
#pragma unroll
            for (int mt=0;mt<4;mt++) {
                int base = (wm + mt*16 + g)*ASTR + ks*8 + tig;
                a[mt][0] = As[base];
                a[mt][1] = As[base + 8*ASTR];
                a[mt][2] = As[base + 4];
                a[mt][3] = As[base + 8*ASTR + 4];
            }
#pragma unroll
            for (int nt=0;nt<4;nt++) {
                int base = (ks*8 + tig)*BSTR + wn + nt*8 + g;
                b[nt][0] = Bs[base];
                b[nt][1] = Bs[base + 4*BSTR];
            }
#pragma unroll
            for (int mt=0;mt<4;mt++)
#pragma unroll
                for (int nt=0;nt<4;nt++)
                    mma_tf32(c[mt][nt], a[mt], b[nt]);
        }
    };

    int ktn = (K+31)>>5;
    load_tile(0, 0);
    asm volatile("cp.async.commit_group;");
    if (ktn > 1) load_tile(1, 32);
    asm volatile("cp.async.commit_group;");
    for (int kt=0; kt<ktn; kt++) {
        asm volatile("cp.async.wait_group 1;");
        __syncthreads();
        if (kt+2 < ktn) load_tile((kt+2)%3, (kt+2)*32);
        asm volatile("cp.async.commit_group;");
        compute(kt%3);
        __syncthreads();
    }

#pragma unroll
    for (int mt=0;mt<4;mt++) {
        long m = m0 + wm + mt*16 + g;
#pragma unroll
        for (int nt=0;nt<4;nt++) {
            int n = n0 + wn + nt*8 + tig*2;
            if (n < N) {
                float bx = bias[n], by = bias[n+1];
                *(__half2*)&C[m*ldc + n] = __floats2half2_rn(c[mt][nt][0]+bx, c[mt][nt][1]+by);
                *(__half2*)&C[(m+8)*ldc + n] = __floats2half2_rn(c[mt][nt][2]+bx, c[mt][nt][3]+by);
            }
        }
    }
}

// ---------------------------------------------------------------------------
// FP16 NT GEMM. OUT16: 0 = fp32 C, 1 = fp16 C. MODE 1: A shared per 2 z.
// ---------------------------------------------------------------------------
#define HSTR 20
#define HA_WORDS (128*HSTR)
#define HSTG (2*HA_WORDS)

template<int MODE, int OUT16>
__launch_bounds__(256, 2)
__global__ void gemm_h(const __half* __restrict__ A, const __half* __restrict__ B,
                       const float* __restrict__ bias, void* __restrict__ Cv,
                       int M, int N, int K,
                       long sA, long sB, long sBias, long sC, int ldc)
{
    extern __shared__ uint32_t smp[];
    int z = blockIdx.z;
    const __half* Ab = A + (MODE==1 ? (long)(z>>1)*sA : (long)z*sA);
    const __half* Bp = B + (long)z*sB;
    const float* bp = bias + (long)z*sBias;

    int m0 = blockIdx.y*128, n0 = blockIdx.x*128;
    int tid = threadIdx.x;
    int warp = tid>>5, lane = tid&31;
    int g = lane>>2, tig = lane&3;
    int wm = (warp&1)*64, wn = (warp>>1)*32;

    float c[4][4][4];
#pragma unroll
    for (int mt=0;mt<4;mt++)
#pragma unroll
        for (int nt=0;nt<4;nt++)
#pragma unroll
            for (int i=0;i<4;i++) c[mt][nt][i]=0.f;

    int lrow = tid>>1;
    int lseg = (tid&1)*8;
    const __half* arow = Ab + (long)(m0+lrow)*K;
    const __half* brow = Bp + (long)(n0+lrow)*K;
    bool bok = (n0+lrow) < N;

    auto load_tile = [&](int st, int k0) {
        uint32_t* As = smp + st*HSTG;
        uint32_t* Bs = As + HA_WORDS;
        cpa16(s2u(&As[lrow*HSTR + lseg]),     arow + k0 + lseg*2,     16);
        cpa16(s2u(&As[lrow*HSTR + lseg + 4]), arow + k0 + lseg*2 + 8, 16);
        cpa16(s2u(&Bs[lrow*HSTR + lseg]),     bok ? (brow + k0 + lseg*2)     : brow, bok?16:0);
        cpa16(s2u(&Bs[lrow*HSTR + lseg + 4]), bok ? (brow + k0 + lseg*2 + 8) : brow, bok?16:0);
    };
    auto compute = [&](int st) {
        const uint32_t* As = smp + st*HSTG;
        const uint32_t* Bs = As + HA_WORDS;
#pragma unroll
        for (int ks=0;ks<2;ks++) {
            uint32_t a[4][4], b[4][2];
#pragma unroll
            for (int mt=0;mt<4;mt++) {
                int base = (wm + mt*16 + g)*HSTR + ks*8 + tig;
                a[mt][0] = As[base];
                a[mt][1] = As[base + 8*HSTR];
                a[mt][2] = As[base + 4];
                a[mt][3] = As[base + 8*HSTR + 4];
            }
#pragma unroll
            for (int nt=0;nt<4;nt++) {
                int base = (wn + nt*8 + g)*HSTR + ks*8 + tig;
                b[nt][0] = Bs[base];
                b[nt][1] = Bs[base + 4];
            }
#pragma unroll
            for (int mt=0;mt<4;mt++)
#pragma unroll
                for (int nt=0;nt<4;nt++)
                    mma_f16(c[mt][nt], a[mt], b[nt]);
        }
    };

    int ktn = K>>5;
    load_tile(0, 0);
    asm volatile("cp.async.commit_group;");
    if (ktn > 1) load_tile(1, 32);
    asm volatile("cp.async.commit_group;");
    for (int kt=0; kt<ktn; kt++) {
        asm volatile("cp.async.wait_group 1;");
        __syncthreads();
        if (kt+2 < ktn) load_tile((kt+2)%3, (kt+2)*32);
        asm volatile("cp.async.commit_group;");
        compute(kt%3);
        __syncthreads();
    }

#pragma unroll
    for (int mt=0;mt<4;mt++) {
        long m = m0 + wm + mt*16 + g;
#pragma unroll
        for (int nt=0;nt<4;nt++) {
            int n = n0 + wn + nt*8 + tig*2;
            if (n < N) {
                float bx = bp[n], by = bp[n+1];
                float v00 = c[mt][nt][0]+bx, v01 = c[mt][nt][1]+by;
                float v10 = c[mt][nt][2]+bx, v11 = c[mt][nt][3]+by;
                if (OUT16) {
                    __half* Cb = (__half*)Cv + (long)z*sC;
                    *(__half2*)&Cb[m*ldc + n] = __floats2half2_rn(v00, v01);
                    *(__half2*)&Cb[(m+8)*ldc + n] = __floats2half2_rn(v10, v11);
                } else {
                    float* Cb = (float*)Cv + (long)z*sC;
                    float2 v0; v0.x = v00; v0.y = v01;
                    float2 v1; v1.x = v10; v1.y = v11;
                    *(float2*)&Cb[m*ldc + n] = v0;
                    *(float2*)&Cb[(m+8)*ldc + n] = v1;
                }
            }
        }
    }
}

// ---------------------------------------------------------------------------
// Fused fp16 QK^T + softmax -> P_h. Block tile 64x256, warp tile 32x64,
// 2 CTAs/SM. grid (1, 4, 384).
// ---------------------------------------------------------------------------
#define QA64 (64*HSTR)             // 1280
#define QB256 (256*HSTR)           // 5120
#define Q64_STG (QA64 + QB256)     // 6400 words per stage

__launch_bounds__(256, 2)
__global__ void qk_softmax_h(const __half* __restrict__ x, __half* __restrict__ P,
                             float scale)
{
    extern __shared__ uint32_t smp[];
    const int qtab[6]  = {0,0,1,1,2,2};
    const int kvtab[6] = {1,2,0,2,0,1};

    int z = blockIdx.z;
    int p = z>>6, b = z&63;
    const __half* Ab = x + ((long)qtab[p]*BS + (long)b*Ss)*128;
    const __half* Bp = x + ((long)kvtab[p]*BS + (long)b*Ss)*128;
    __half* Cb = P + (long)z*Ss*Ss;
    int m0 = blockIdx.y*64;
    int tid = threadIdx.x;
    int warp = tid>>5, lane = tid&31;
    int g = lane>>2, tig = lane&3;
    int wm = (warp&1)*32, wn = (warp>>1)*64;

    float c[2][8][4];
#pragma unroll
    for (int mt=0;mt<2;mt++)
#pragma unroll
        for (int nt=0;nt<8;nt++)
#pragma unroll
            for (int i=0;i<4;i++) c[mt][nt][i]=0.f;

    int arow_i = tid>>2;            // 0..63
    int aseg = (tid&3)*4;           // word offset 0,4,8,12
    const __half* arow = Ab + (long)(m0+arow_i)*128;
    const __half* brow = Bp + (long)tid*128;

    auto load_tile = [&](int st, int k0) {
        uint32_t* As = smp + st*Q64_STG;
        uint32_t* Bs = As + QA64;
        cpa16(s2u(&As[arow_i*HSTR + aseg]), arow + k0 + aseg*2, 16);
#pragma unroll
        for (int h=0;h<4;h++)
            cpa16(s2u(&Bs[tid*HSTR + h*4]), brow + k0 + h*8, 16);
    };
    auto compute = [&](int st) {
        const uint32_t* As = smp + st*Q64_STG;
        const uint32_t* Bs = As + QA64;
#pragma unroll
        for (int ks=0;ks<2;ks++) {
            uint32_t a[2][4], bb[8][2];
#pragma unroll
            for (int mt=0;mt<2;mt++) {
                int base = (wm + mt*16 + g)*HSTR + ks*8 + tig;
                a[mt][0] = As[base];
                a[mt][1] = As[base + 8*HSTR];
                a[mt][2] = As[base + 4];
                a[mt][3] = As[base + 8*HSTR + 4];
            }
#pragma unroll
            for (int nt=0;nt<8;nt++) {
                int base = (wn + nt*8 + g)*HSTR + ks*8 + tig;
                bb[nt][0] = Bs[base];
                bb[nt][1] = Bs[base + 4];
            }
#pragma unroll
            for (int mt=0;mt<2;mt++)
#pragma unroll
                for (int nt=0;nt<8;nt++)
                    mma_f16(c[mt][nt], a[mt], bb[nt]);
        }
    };

    load_tile(0, 0);
    asm volatile("cp.async.commit_group;");
    load_tile(1, 32);
    asm volatile("cp.async.commit_group;");
    for (int kt=0; kt<4; kt++) {
        asm volatile("cp.async.wait_group 1;");
        __syncthreads();
        if (kt+2 < 4) load_tile((kt+2)%3, (kt+2)*32);
        asm volatile("cp.async.commit_group;");
        compute(kt%3);
        __syncthreads();
    }

    // ---- fused softmax over 256 cols (rows local 0..63) ----
#pragma unroll
    for (int mt=0;mt<2;mt++)
#pragma unroll
        for (int nt=0;nt<8;nt++)
#pragma unroll
            for (int i=0;i<4;i++) c[mt][nt][i] *= scale;

    float* red = (float*)smp;       // [64][4]
    int wcol = warp>>1;
    float rmax[2][2], rinv[2][2];

#pragma unroll
    for (int mt=0;mt<2;mt++)
#pragma unroll
        for (int h=0;h<2;h++) {
            float m = -1e30f;
#pragma unroll
            for (int nt=0;nt<8;nt++)
                m = fmaxf(m, fmaxf(c[mt][nt][2*h], c[mt][nt][2*h+1]));
            m = fmaxf(m, __shfl_xor_sync(0xffffffffu, m, 1));
            m = fmaxf(m, __shfl_xor_sync(0xffffffffu, m, 2));
            if (tig == 0) red[(wm + mt*16 + g + h*8)*4 + wcol] = m;
        }
    __syncthreads();
#pragma unroll
    for (int mt=0;mt<2;mt++)
#pragma unroll
        for (int h=0;h<2;h++) {
            int r = wm + mt*16 + g + h*8;
            rmax[mt][h] = fmaxf(fmaxf(red[r*4], red[r*4+1]),
                                fmaxf(red[r*4+2], red[r*4+3]));
        }
    __syncthreads();
#pragma unroll
    for (int mt=0;mt<2;mt++)
#pragma unroll
        for (int h=0;h<2;h++) {
            float s = 0.f;
#pragma unroll
            for (int nt=0;nt<8;nt++) {
                float e0 = __expf(c[mt][nt][2*h]   - rmax[mt][h]);
                float e1 = __expf(c[mt][nt][2*h+1] - rmax[mt][h]);
                c[mt][nt][2*h]   = e0;
                c[mt][nt][2*h+1] = e1;
                s += e0 + e1;
            }
            s += __shfl_xor_sync(0xffffffffu, s, 1);
            s += __shfl_xor_sync(0xffffffffu, s, 2);
            if (tig == 0) red[(wm + mt*16 + g + h*8)*4 + wcol] = s;
        }
    __syncthreads();
#pragma unroll
    for (int mt=0;mt<2;mt++)
#pragma unroll
        for (int h=0;h<2;h++) {
            int r = wm + mt*16 + g + h*8;
            rinv[mt][h] = 1.f/(red[r*4] + red[r*4+1] + red[r*4+2] + red[r*4+3]);
        }
#pragma unroll
    for (int mt=0;mt<2;mt++)
#pragma unroll
        for (int h=0;h<2;h++) {
            long row = m0 + wm + mt*16 + g + h*8;
#pragma unroll
            for (int nt=0;nt<8;nt++) {
                int col = wn + nt*8 + tig*2;
                *(__half2*)&Cb[row*256 + col] =
                    __floats2half2_rn(c[mt][nt][2*h]   * rinv[mt][h],
                                      c[mt][nt][2*h+1] * rinv[mt][h]);
            }
        }
}

// ---------------------------------------------------------------------------
// Merged PV (fp16), continuous 16-ktile pipeline over both KV segments.
// ---------------------------------------------------------------------------
__launch_bounds__(256, 2)
__global__ void pv_h(const __half* __restrict__ P, const __half* __restrict__ xT,
                     float* __restrict__ tstep, __half* __restrict__ tstep_h)
{
    extern __shared__ uint32_t smp[];
    const int kvtab[6] = {1,2,0,2,0,1};
    int z = blockIdx.z;
    int qq = z>>6, b = z&63;
    float* Cb = tstep + (long)qq*128 + (long)b*Ss*384;
    __half* Ch = tstep_h + (long)qq*128 + (long)b*Ss*384;

    int m0 = blockIdx.y*128;
    int tid = threadIdx.x;
    int warp = tid>>5, lane = tid&31;
    int g = lane>>2, tig = lane&3;
    int wm = (warp&1)*64, wn = (warp>>1)*32;

    float c[4][4][4];
#pragma unroll
    for (int mt=0;mt<4;mt++)
#pragma unroll
        for (int nt=0;nt<4;nt++)
#pragma unroll
            for (int i=0;i<4;i++) c[mt][nt][i]=0.f;

    int lrow = tid>>1;
    int lseg = (tid&1)*8;

    auto load_tile = [&](int st, int gk) {
        int p = 2*qq + (gk>>3);
        int k0 = (gk&7)*32;
        const __half* ar = P + ((long)p*64 + b)*(long)Ss*Ss + (long)(m0+lrow)*Ss + k0;
        const __half* br = xT + ((long)kvtab[p]*64 + b)*128l*Ss + (long)lrow*Ss + k0;
        uint32_t* As = smp + st*HSTG;
        uint32_t* Bs = As + HA_WORDS;
        cpa16(s2u(&As[lrow*HSTR + lseg]),     ar + lseg*2,     16);
        cpa16(s2u(&As[lrow*HSTR + lseg + 4]), ar + lseg*2 + 8, 16);
        cpa16(s2u(&Bs[lrow*HSTR + lseg]),     br + lseg*2,     16);
        cpa16(s2u(&Bs[lrow*HSTR + lseg + 4]), br + lseg*2 + 8, 16);
    };
    auto compute = [&](int st) {
        const uint32_t* As = smp + st*HSTG;
        const uint32_t* Bs = As + HA_WORDS;
#pragma unroll
        for (int ks=0;ks<2;ks++) {
            uint32_t a[4][4], bb[4][2];
#pragma unroll
            for (int mt=0;mt<4;mt++) {
                int base = (wm + mt*16 + g)*HSTR + ks*8 + tig;
                a[mt][0] = As[base];
                a[mt][1] = As[base + 8*HSTR];
                a[mt][2] = As[base + 4];
                a[mt][3] = As[base + 8*HSTR + 4];
            }
#pragma unroll
            for (int nt=0;nt<4;nt++) {
                int base = (wn + nt*8 + g)*HSTR + ks*8 + tig;
                bb[nt][0] = Bs[base];
                bb[nt][1] = Bs[base + 4];
            }
#pragma unroll
            for (int mt=0;mt<4;mt++)
#pragma unroll
                for (int nt=0;nt<4;nt++)
                    mma_f16(c[mt][nt], a[mt], bb[nt]);
        }
    };

    load_tile(0, 0);
    asm volatile("cp.async.commit_group;");
    load_tile(1, 1);
    asm volatile("cp.async.commit_group;");
    for (int gk=0; gk<16; gk++) {
        asm volatile("cp.async.wait_group 1;");
        __syncthreads();
        if (gk+2 < 16) load_tile((gk+2)%3, gk+2);
        asm volatile("cp.async.commit_group;");
        compute(gk%3);
        __syncthreads();
    }

#pragma unroll
    for (int mt=0;mt<4;mt++) {
        long m = m0 + wm + mt*16 + g;
#pragma unroll
        for (int nt=0;nt<4;nt++) {
            int n = wn + nt*8 + tig*2;
            float2 o0 = *(const float2*)&Cb[m*384 + n];
            float2 o1 = *(const float2*)&Cb[(m+8)*384 + n];
            float2 v0, v1;
            v0.x = c[mt][nt][0]+o0.x; v0.y = c[mt][nt][1]+o0.y;
            v1.x = c[mt][nt][2]+o1.x; v1.y = c[mt][nt][3]+o1.y;
            *(float2*)&Cb[m*384 + n] = v0;
            *(float2*)&Cb[(m+8)*384 + n] = v1;
            *(__half2*)&Ch[m*384 + n] = __floats2half2_rn(v0.x, v0.y);
            *(__half2*)&Ch[(m+8)*384 + n] = __floats2half2_rn(v1.x, v1.y);
        }
    }
}

// ---------------------------------------------------------------------------
// biGRU with next-step xg register prefetch.
// ---------------------------------------------------------------------------
__launch_bounds__(192, 3)
__global__ void gru_rec(const float* __restrict__ xg_all, const float* __restrict__ Wh,
                        const float* __restrict__ bh, __half* __restrict__ x_h,
                        float* __restrict__ tstep)
{
    int bx = blockIdx.x;
    int m = bx>>7, d = (bx>>6)&1, b = bx&63, md = m*2+d;
    int j = threadIdx.x;
    ull w2[32];
#pragma unroll
    for (int q=0;q<32;q++)
        w2[q] = pk(Wh[((long)md*64 + 2*q)*192 + j], Wh[((long)md*64 + 2*q+1)*192 + j]);
    float bhj = bh[md*192 + j];
    __shared__ alignas(16) float h_s[64];
    __shared__ float pre_s[192], xn_s[64];
    uint32_t hsa = s2u(h_s);
    if (j<64) h_s[j]=0.f;
    const float* xg = xg_all + ((long)md*BS + (long)b*Ss)*192;
    int s0 = d ? (Ss-1) : 0;
    float xg_cur = xg[(long)s0*192 + j];
    for (int t=0;t<Ss;t++) {
        int s = d ? (Ss-1-t) : t;
        int sn = d ? (Ss-2-t) : (t+1);
        sn = sn < 0 ? 0 : (sn > Ss-1 ? Ss-1 : sn);
        __syncthreads();
        float xg_nxt = xg[(long)sn*192 + j];
        ull a0 = pk(bhj, 0.f), a1 = pk(0.f, 0.f);
#pragma unroll
        for (int q=0;q<16;q++) {
            ull h0,h1; lds2x64(h0,h1, hsa + q*16);
            ffma2(a0, h0, w2[2*q]);
            ffma2(a1, h1, w2[2*q+1]);
        }
        float2 f0 = upk(a0), f1 = upk(a1);
        float acc = f0.x + f0.y + f1.x + f1.y;
        float xgv = xg_cur;
        if (j<128) pre_s[j] = acc + xgv;
        else { pre_s[j] = acc; xn_s[j-128] = xgv; }
        __syncthreads();
        if (j<64) {
            float r = sigf(pre_s[j]);
            float zg = sigf(pre_s[64+j]);
            float n = tanhfast(xn_s[j] + r*pre_s[128+j]);
            float hn = (1.f-zg)*n + zg*h_s[j];
            h_s[j] = hn;
            long row = (long)b*Ss + s;
            x_h[((long)m*BS + row)*128 + d*64 + j] = __float2half(hn);
            tstep[row*384 + m*128 + d*64 + j] = hn;
        }
        xg_cur = xg_nxt;
    }
}

// ---------------------------------------------------------------------------
// biLSTM with next-step xg register prefetch.
// ---------------------------------------------------------------------------
__launch_bounds__(512, 1)
__global__ void lstm_rec(const float* __restrict__ xg_all, const float* __restrict__ Wh,
                         const float* __restrict__ bh, __half* __restrict__ sf_h)
{
    extern __shared__ unsigned char smraw[];
    ull*   Wlo2  = (ull*)smraw;
    float* h_s   = (float*)(smraw + 16*512*8);
    float* pre_s = (float*)(smraw + 16*512*8 + 512);
    int bx = blockIdx.x, d = bx>>6, b = bx&63;
    int j = threadIdx.x;
    const float* Whd = Wh + (long)d*128*512;
    ull w2[48];
#pragma unroll
    for (int q=0;q<48;q++)
        w2[q] = pk(Whd[(long)(2*q)*512 + j], Whd[(long)(2*q+1)*512 + j]);
    for (int q=0;q<16;q++)
        Wlo2[q*512 + j] = pk(Whd[(long)(96+2*q)*512 + j], Whd[(long)(97+2*q)*512 + j]);
    float bhj = bh[d*512 + j];
    float c = 0.f;
    if (j<128) h_s[j]=0.f;
    uint32_t hsa = s2u(h_s);
    const float* xg = xg_all + ((long)d*BS + (long)b*Ss)*512;
    int s0 = d ? (Ss-1) : 0;
    float xg_cur = xg[(long)s0*512 + j];
    for (int t=0;t<Ss;t++) {
        int s = d ? (Ss-1-t) : t;
        int sn = d ? (Ss-2-t) : (t+1);
        sn = sn < 0 ? 0 : (sn > Ss-1 ? Ss-1 : sn);
        __syncthreads();
        float xg_nxt = xg[(long)sn*512 + j];
        ull a0 = pk(bhj, 0.f), a1 = pk(0.f, 0.f);
#pragma unroll
        for (int q=0;q<24;q++) {
            ull h0,h1; lds2x64(h0,h1, hsa + q*16);
            ffma2(a0, h0, w2[2*q]);
            ffma2(a1, h1, w2[2*q+1]);
        }
#pragma unroll
        for (int q=0;q<8;q++) {
            ull h0,h1; lds2x64(h0,h1, hsa + 384 + q*16);
            ffma2(a0, h0, Wlo2[(2*q)*512 + j]);
            ffma2(a1, h1, Wlo2[(2*q+1)*512 + j]);
        }
        float2 f0 = upk(a0), f1 = upk(a1);
        float acc = f0.x + f0.y + f1.x + f1.y + xg_cur;
        pre_s[j] = acc;
        __syncthreads();
        if (j<128) {
            float ig = pre_s[j], fg = pre_s[128+j], gg = pre_s[256+j], og = pre_s[384+j];
            c = sigf(fg)*c + sigf(ig)*tanhfast(gg);
            float h = sigf(og)*tanhfast(c);
            h_s[j] = h;
            sf_h[((long)b*Ss + s)*256 + d*128 + j] = __float2half(h);
        }
        xg_cur = xg_nxt;
    }
}

// ---------------------------------------------------------------------------
// RGN with next-step xg register prefetch.
// ---------------------------------------------------------------------------
__launch_bounds__(384, 1)
__global__ void rgn_rec(const float* __restrict__ xg_all, const float* __restrict__ Wh,
                        const float* __restrict__ state0, const float* __restrict__ state1,
                        float* __restrict__ outbuf)
{
    __shared__ alignas(16) float h_s[128];
    __shared__ float pre_s[384], xn_s[128];
    int bx = blockIdx.x, kk = bx>>6, b = bx&63;
    int j = threadIdx.x;
    const float* Whd = Wh + (long)kk*128*384;
    ull w2[64];
#pragma unroll
    for (int q=0;q<64;q++)
        w2[q] = pk(Whd[(long)(2*q)*384 + j], Whd[(long)(2*q+1)*384 + j]);
    if (j<128) h_s[j] = (kk==0?state0:state1)[b*128 + j];
    uint32_t hsa = s2u(h_s);
    const float* xg = xg_all + ((long)kk*BS + (long)b*Ss)*384;
    int s0 = kk ? (Ss-1) : 0;
    float xg_cur = xg[(long)s0*384 + j];
    for (int t=0;t<Ss;t++) {
        int sn = kk ? (Ss-2-t) : (t+1);
        sn = sn < 0 ? 0 : (sn > Ss-1 ? Ss-1 : sn);
        __syncthreads();
        float xg_nxt = xg[(long)sn*384 + j];
        ull a0 = pk(0.f, 0.f), a1 = pk(0.f, 0.f);
#pragma unroll
        for (int q=0;q<32;q++) {
            ull h0,h1; lds2x64(h0,h1, hsa + q*16);
            ffma2(a0, h0, w2[2*q]);
            ffma2(a1, h1, w2[2*q+1]);
        }
        float2 f0 = upk(a0), f1 = upk(a1);
        float acc = f0.x + f0.y + f1.x + f1.y;
        float xgv = xg_cur;
        if (j<256) pre_s[j] = acc + xgv;
        else { pre_s[j] = acc; xn_s[j-256] = xgv; }
        __syncthreads();
        if (j<128) {
            float r = sigf(pre_s[j]);
            float z = sigf(pre_s[128+j]);
            float n = tanhfast(xn_s[j] + r*pre_s[256+j]);
            h_s[j] = (1.f-z)*n + z*h_s[j];
        }
        xg_cur = xg_nxt;
    }
    __syncthreads();
    if (j<128) outbuf[((long)kk*64 + b)*128 + j] = h_s[j];
}

__launch_bounds__(32)
__global__ void final_fc(const float* __restrict__ outbuf,
                         const float* __restrict__ fc1W, const float* __restrict__ fc1b,
                         const float* __restrict__ fc2W, const float* __restrict__ fc2b,
                         float* __restrict__ out)
{
    int b = blockIdx.x, t = threadIdx.x;
    float acc = fc1b[t];
    for (int k=0;k<128;k++) {
        float x = outbuf[b*128+k] + outbuf[64*128 + b*128 + k];
        acc += x * fc1W[k*32 + t];
    }
    float h = acc > 0.f ? acc : 0.01f*acc;
    float v = h * fc2W[t];
#pragma unroll
    for (int o=16;o;o>>=1) v += __shfl_xor_sync(0xffffffffu, v, o);
    if (t==0) out[b] = v + fc2b[0];
}

extern "C" void kernel_launch(void* const* d_in, const int* in_sizes, int n_in,
                              void* d_out, int out_size)
{
    (void)in_sizes; (void)n_in; (void)out_size;
    const int*   sentences = (const int*)  d_in[0];
    const float* acoustic  = (const float*)d_in[1];
    const float* video     = (const float*)d_in[2];
    const float* state0    = (const float*)d_in[3];
    const float* state1    = (const float*)d_in[4];
    const float* emb       = (const float*)d_in[5];
    const float* proj_l_W  = (const float*)d_in[6];
    const float* proj_l_b  = (const float*)d_in[7];
    const float* proj_a_W  = (const float*)d_in[8];
    const float* proj_a_b  = (const float*)d_in[9];
    const float* proj_v_W  = (const float*)d_in[10];
    const float* proj_v_b  = (const float*)d_in[11];
    const float* gru_Wi    = (const float*)d_in[12];
    const float* gru_Wh    = (const float*)d_in[13];
    const float* gru_bi    = (const float*)d_in[14];
    const float* gru_bh    = (const float*)d_in[15];
    const float* lstm_Wi   = (const float*)d_in[16];
    const float* lstm_Wh   = (const float*)d_in[17];
    const float* lstm_bi   = (const float*)d_in[18];
    const float* lstm_bh   = (const float*)d_in[19];
    const float* rgn_Wx    = (const float*)d_in[20];
    const float* rgn_Wh    = (const float*)d_in[21];
    const float* rgn_b     = (const float*)d_in[22];
    const float* fc1_W     = (const float*)d_in[23];
    const float* fc1_b     = (const float*)d_in[24];
    const float* fc2_W     = (const float*)d_in[25];
    const float* fc2_b     = (const float*)d_in[26];
    float* out = (float*)d_out;

    float *xg_gru,*tstep,*xg_lstm,*xg_rgn,*rgn_out;
    __half *seq_h,*x_h,*xT_h,*P_h,*tstep_h,*sf_h,*WT_h,*ac_h,*vid_h;
    cudaGetSymbolAddress((void**)&xg_gru, g_xg_gru);
    cudaGetSymbolAddress((void**)&tstep, g_tstep);
    cudaGetSymbolAddress((void**)&xg_lstm, g_xg_lstm);
    cudaGetSymbolAddress((void**)&xg_rgn, g_xg_rgn);
    cudaGetSymbolAddress((void**)&rgn_out, g_rgn_out);
    cudaGetSymbolAddress((void**)&seq_h, g_seq_h);
    cudaGetSymbolAddress((void**)&x_h, g_x_h);
    cudaGetSymbolAddress((void**)&xT_h, g_xT_h);
    cudaGetSymbolAddress((void**)&P_h, g_P_h);
    cudaGetSymbolAddress((void**)&tstep_h, g_tstep_h);
    cudaGetSymbolAddress((void**)&sf_h, g_sf_h);
    cudaGetSymbolAddress((void**)&WT_h, g_WT_h);
    cudaGetSymbolAddress((void**)&ac_h, g_ac_h);
    cudaGetSymbolAddress((void**)&vid_h, g_vid_h);
    __half* gruT  = WT_h;
    __half* lstmT = gruT + 6*192*128;
    __half* rgnT  = lstmT + 2l*512*384;
    __half* projaT = rgnT + 2l*384*256;
    __half* projvT = projaT + 128*96;

    const size_t shm_tf3 = 3u*STG_WORDS*4u;
    const size_t shm_h   = 3u*HSTG*4u;
    const size_t shm_qk  = 3u*Q64_STG*4u;   // 76800
    cudaFuncSetAttribute(gemm_tf, cudaFuncAttributeMaxDynamicSharedMemorySize, (int)shm_tf3);
    cudaFuncSetAttribute(gemm_h<0,0>, cudaFuncAttributeMaxDynamicSharedMemorySize, (int)shm_h);
    cudaFuncSetAttribute(gemm_h<1,0>, cudaFuncAttributeMaxDynamicSharedMemorySize, (int)shm_h);
    cudaFuncSetAttribute(gemm_h<0,1>, cudaFuncAttributeMaxDynamicSharedMemorySize, (int)shm_h);
    cudaFuncSetAttribute(qk_softmax_h, cudaFuncAttributeMaxDynamicSharedMemorySize, (int)shm_qk);
    cudaFuncSetAttribute(pv_h, cudaFuncAttributeMaxDynamicSharedMemorySize, (int)shm_h);
    cudaFuncSetAttribute(lstm_rec, cudaFuncAttributeMaxDynamicSharedMemorySize, 72*1024);

    // all weight transposes + input conversions (2 launches total)
    wtrans_all<<<740, dim3(32,8)>>>(gru_Wi, lstm_Wi, rgn_Wx, proj_a_W, proj_v_W, WT_h);
    conv2<<<1024, 256>>>(acoustic, ac_h, video, vid_h);

    // modality projections -> seq_h
    gemm_tf<<<dim3(1, BS/128, 1), 256, shm_tf3>>>(
        emb, proj_l_W, proj_l_b, seq_h, BS, 128, DL, 128, sentences);
    gemm_h<0,1><<<dim3(1, BS/128, 1), 256, shm_h>>>(
        ac_h, projaT, proj_a_b, seq_h + 1l*BS*DH, BS, 128, 96, 0, 0, 0, 0, 128);
    gemm_h<0,1><<<dim3(1, BS/128, 1), 256, shm_h>>>(
        vid_h, projvT, proj_v_b, seq_h + 2l*BS*DH, BS, 128, 64, 0, 0, 0, 0, 128);

    // GRU input projections (z=6)
    gemm_h<1,0><<<dim3(2, BS/128, 6), 256, shm_h>>>(
        seq_h, gruT, gru_bi, xg_gru, BS, 192, 128,
        (long)BS*DH, 192l*128, 192, (long)BS*192, 192);

    gru_rec<<<3*2*64, 192>>>(xg_gru, gru_Wh, gru_bh, x_h, tstep);
    xtrans<<<dim3(192, 4), 256>>>(x_h, xT_h);

    // JCAF
    const float scale = 0.08838834764831845f;
    qk_softmax_h<<<dim3(1, 4, 384), 256, shm_qk>>>(x_h, P_h, scale);
    pv_h<<<dim3(1, 2, 192), 256, shm_h>>>(P_h, xT_h, tstep, tstep_h);

    // LSTM input projections (z=2)
    gemm_h<0,0><<<dim3(4, BS/128, 2), 256, shm_h>>>(
        tstep_h, lstmT, lstm_bi, xg_lstm, BS, 512, 384,
        0, 512l*384, 512, (long)BS*512, 512);

    lstm_rec<<<2*64, 512, 16*512*8 + 512 + 2048>>>(xg_lstm, lstm_Wh, lstm_bh, sf_h);

    // RGN input projections (z=2)
    gemm_h<0,0><<<dim3(3, BS/128, 2), 256, shm_h>>>(
        sf_h, rgnT, rgn_b, xg_rgn, BS, 384, 256,
        0, 384l*256, 384, (long)BS*384, 384);

    rgn_rec<<<2*64, 384>>>(xg_rgn, rgn_Wh, state0, state1, rgn_out);

    final_fc<<<Bb, 32>>>(rgn_out, fc1_W, fc1_b, fc2_W, fc2_b, out);
}